// round 1
// baseline (speedup 1.0000x reference)
#include <cuda_runtime.h>
#include <cuda_bf16.h>
#include <math.h>

// Problem constants
#define Bz 4
#define Sz 4096
#define Ez 512
#define Hz 8
#define Dz 64
#define Mz 2048
#define Lz 6
#define Nrows (Bz*Sz)          // 16384
#define LN_EPS 1e-6f
#define KEPS 1e-3f

// ---------------- device scratch (no allocations allowed) ----------------
__device__ float g_x[Nrows*Ez];     // residual stream
__device__ float g_h[Nrows*Ez];     // LN output
__device__ float g_phiq[Nrows*Ez];
__device__ float g_phik[Nrows*Ez];
__device__ float g_v[Nrows*Ez];     // v, then reused as attention output
__device__ float g_t[Nrows*Mz];     // FFN mid
__device__ float g_kv[Bz*Hz*Dz*Dz];
__device__ float g_z[Bz*Hz*Dz];

// ---------------- embedding + sinusoidal PE ----------------
__global__ void embed_pe_kernel(const int* __restrict__ inp,
                                const float* __restrict__ emb,
                                float* __restrict__ x) {
    int idx = blockIdx.x * blockDim.x + threadIdx.x;
    if (idx >= Nrows * Ez) return;
    int e = idx & (Ez - 1);
    int n = idx >> 9;           // / Ez
    int s = n & (Sz - 1);
    int tok = inp[n];
    int j = (e >> 1) * 2;
    const float c = -9.210340371976184f / (float)Ez;   // -ln(10000)/E
    float ang = (float)s * expf((float)j * c);
    float pe = (e & 1) ? cosf(ang) : sinf(ang);
    x[idx] = emb[(size_t)tok * Ez + e] + pe;
}

// ---------------- layernorm (one block per row, 256 thr, 2 elems/thr) ----
__device__ __forceinline__ float block_sum(float val, float* red) {
    __syncthreads();
    int t = threadIdx.x;
    #pragma unroll
    for (int o = 16; o; o >>= 1) val += __shfl_down_sync(0xffffffffu, val, o);
    if ((t & 31) == 0) red[t >> 5] = val;
    __syncthreads();
    if (t < 32) {
        float r = (t < 8) ? red[t] : 0.f;
        #pragma unroll
        for (int o = 4; o; o >>= 1) r += __shfl_down_sync(0xffffffffu, r, o);
        if (t == 0) red[0] = r;
    }
    __syncthreads();
    return red[0];
}

__global__ void layernorm_kernel(const float* __restrict__ in,
                                 float* __restrict__ out,
                                 const float* __restrict__ scale,
                                 const float* __restrict__ bias) {
    __shared__ float red[32];
    int n = blockIdx.x;
    int t = threadIdx.x;
    const float* row = in + (size_t)n * Ez;
    float2 v = *(const float2*)&row[t * 2];
    float mu = block_sum(v.x + v.y, red) * (1.f / Ez);
    float dx = v.x - mu, dy = v.y - mu;
    float var = block_sum(dx * dx + dy * dy, red) * (1.f / Ez);
    float rs = rsqrtf(var + LN_EPS);
    float2 o;
    o.x = dx * rs * scale[t * 2 + 0] + bias[t * 2 + 0];
    o.y = dy * rs * scale[t * 2 + 1] + bias[t * 2 + 1];
    *(float2*)&out[(size_t)n * Ez + t * 2] = o;
}

// ---------------- generic tiled GEMM: C[Nr,NC] = A[Nr,K] @ W[K,NC] --------
// BM=BN=64, BK=16, 256 threads, 4x4 per thread.
// EPI: 0 plain, 1 relu+eps, 2 (relu+eps)*mask, 3 gelu(x+bias),
//      4 x+bias+resid, 5 x+resid
__device__ __forceinline__ float gelu_tanh(float x) {
    float x3 = x * x * x;
    return 0.5f * x * (1.f + tanhf(0.7978845608028654f * (x + 0.044715f * x3)));
}

template<int EPI>
__global__ void gemm64(const float* __restrict__ A, const float* __restrict__ W,
                       float* __restrict__ C, int K, int NC,
                       const float* __restrict__ bias,
                       const float* __restrict__ resid,
                       const int* __restrict__ maskTok) {
    __shared__ float As[16][64];
    __shared__ float Bs[16][64];
    int tid = threadIdx.x;
    int tx = tid & 15, ty = tid >> 4;
    int rowBase = blockIdx.y * 64;
    int colBase = blockIdx.x * 64;

    float acc[4][4];
    #pragma unroll
    for (int i = 0; i < 4; i++)
        #pragma unroll
        for (int j = 0; j < 4; j++) acc[i][j] = 0.f;

    int ar = tid >> 2;            // 0..63 (row in A tile)
    int akq = (tid & 3) * 4;      // k offset
    int brk = tid >> 4;           // 0..15 (k row in B tile)
    int bcq = (tid & 15) * 4;     // col offset

    for (int k0 = 0; k0 < K; k0 += 16) {
        float4 a4 = *(const float4*)&A[(size_t)(rowBase + ar) * K + k0 + akq];
        As[akq + 0][ar] = a4.x;
        As[akq + 1][ar] = a4.y;
        As[akq + 2][ar] = a4.z;
        As[akq + 3][ar] = a4.w;
        *(float4*)&Bs[brk][bcq] =
            *(const float4*)&W[(size_t)(k0 + brk) * NC + colBase + bcq];
        __syncthreads();
        #pragma unroll
        for (int kk = 0; kk < 16; kk++) {
            float a[4], b[4];
            #pragma unroll
            for (int i = 0; i < 4; i++) { a[i] = As[kk][ty * 4 + i]; b[i] = Bs[kk][tx * 4 + i]; }
            #pragma unroll
            for (int i = 0; i < 4; i++)
                #pragma unroll
                for (int j = 0; j < 4; j++) acc[i][j] = fmaf(a[i], b[j], acc[i][j]);
        }
        __syncthreads();
    }

    #pragma unroll
    for (int i = 0; i < 4; i++) {
        int r = rowBase + ty * 4 + i;
        float m = 1.f;
        if (EPI == 2) m = (maskTok[r] > 0) ? 1.f : 0.f;
        #pragma unroll
        for (int j = 0; j < 4; j++) {
            int c = colBase + tx * 4 + j;
            float val = acc[i][j];
            if (EPI == 1) val = fmaxf(val, 0.f) + KEPS;
            if (EPI == 2) val = (fmaxf(val, 0.f) + KEPS) * m;
            if (EPI == 3) val = gelu_tanh(val + bias[c]);
            if (EPI == 4) val = val + bias[c] + resid[(size_t)r * NC + c];
            if (EPI == 5) val = val + resid[(size_t)r * NC + c];
            C[(size_t)r * NC + c] = val;
        }
    }
}

// ---------------- zero kv/z -----------------------------------------------
__global__ void zero_kv_kernel(float* kv, float* z) {
    int i = blockIdx.x * blockDim.x + threadIdx.x;
    if (i < Bz * Hz * Dz * Dz) kv[i] = 0.f;
    if (i < Bz * Hz * Dz) z[i] = 0.f;
}

// ---------------- kv = phik^T @ v (per b,h), z = sum phik ------------------
#define KV_SPLITS 8
__global__ void kv_kernel(const float* __restrict__ phik,
                          const float* __restrict__ v,
                          float* __restrict__ kv, float* __restrict__ z) {
    int bh = blockIdx.x;              // 0..31
    int split = blockIdx.y;           // 0..KV_SPLITS-1
    int b = bh >> 3, h = bh & 7;
    const int CH = Sz / KV_SPLITS;    // 512
    int s0 = split * CH;
    __shared__ float ks[32][64];
    __shared__ float vs[32][64];
    int tid = threadIdx.x;
    int tx = tid & 15, ty = tid >> 4;

    float acc[4][4];
    #pragma unroll
    for (int i = 0; i < 4; i++)
        #pragma unroll
        for (int j = 0; j < 4; j++) acc[i][j] = 0.f;
    float zacc[4] = {0.f, 0.f, 0.f, 0.f};

    for (int c = 0; c < CH; c += 32) {
        #pragma unroll
        for (int r = 0; r < 2; r++) {
            int f4 = tid + r * 256;       // 512 float4s = 32x64 floats
            int row = f4 >> 4;
            int col = (f4 & 15) * 4;
            size_t base = ((size_t)(b * Sz + s0 + c + row)) * Ez + h * 64 + col;
            *(float4*)&ks[row][col] = *(const float4*)&phik[base];
            *(float4*)&vs[row][col] = *(const float4*)&v[base];
        }
        __syncthreads();
        #pragma unroll
        for (int s = 0; s < 32; s++) {
            float a[4], bb[4];
            #pragma unroll
            for (int i = 0; i < 4; i++) { a[i] = ks[s][ty * 4 + i]; bb[i] = vs[s][tx * 4 + i]; }
            #pragma unroll
            for (int i = 0; i < 4; i++)
                #pragma unroll
                for (int j = 0; j < 4; j++) acc[i][j] = fmaf(a[i], bb[j], acc[i][j]);
            if (tx == 0) {
                #pragma unroll
                for (int i = 0; i < 4; i++) zacc[i] += a[i];
            }
        }
        __syncthreads();
    }
    float* kvp = kv + bh * Dz * Dz;
    #pragma unroll
    for (int i = 0; i < 4; i++)
        #pragma unroll
        for (int j = 0; j < 4; j++)
            atomicAdd(&kvp[(ty * 4 + i) * 64 + tx * 4 + j], acc[i][j]);
    if (tx == 0) {
        #pragma unroll
        for (int i = 0; i < 4; i++)
            atomicAdd(&z[bh * 64 + ty * 4 + i], zacc[i]);
    }
}

// ---------------- out = (phiq @ kv) / (phiq . z) ---------------------------
__global__ void numden_kernel(const float* __restrict__ phiq,
                              const float* __restrict__ kv,
                              const float* __restrict__ z,
                              float* __restrict__ out) {
    int bh = blockIdx.x;          // 0..31
    int chunk = blockIdx.y;       // 64 rows each
    int b = bh >> 3, h = bh & 7;
    __shared__ float kvs[64][64];
    __shared__ float zs[64];
    __shared__ float pqs[4][64];
    int tid = threadIdx.x;
    int tx = tid & 63, ty = tid >> 6;

    #pragma unroll
    for (int r = 0; r < 4; r++) {
        int f4 = tid + r * 256;       // 1024 float4s = 64x64
        int row = f4 >> 4;
        int col = (f4 & 15) * 4;
        *(float4*)&kvs[row][col] = *(const float4*)&kv[bh * Dz * Dz + row * 64 + col];
    }
    if (tid < 64) zs[tid] = z[bh * 64 + tid];
    __syncthreads();

    int s0 = chunk * 64;
    for (int it = 0; it < 16; it++) {
        int s = s0 + it * 4 + ty;
        size_t base = ((size_t)(b * Sz + s)) * Ez + h * 64;
        pqs[ty][tx] = phiq[base + tx];
        __syncthreads();
        float num = 0.f, den = 0.f;
        #pragma unroll
        for (int m = 0; m < 64; m++) {
            float p = pqs[ty][m];
            num = fmaf(p, kvs[m][tx], num);
            den = fmaf(p, zs[m], den);
        }
        out[base + tx] = num / den;
        __syncthreads();
    }
}

// ---------------- host side ------------------------------------------------
extern "C" void kernel_launch(void* const* d_in, const int* in_sizes, int n_in,
                              void* d_out, int out_size) {
    const int*   inputs    = (const int*)  d_in[0];   // [B,S]
    const float* embed     = (const float*)d_in[1];   // [V,E]
    const float* ln1_scale = (const float*)d_in[2];   // [L,E]
    const float* ln1_bias  = (const float*)d_in[3];
    const float* wq        = (const float*)d_in[4];   // [L,E,H,D]
    const float* wk        = (const float*)d_in[5];
    const float* wv        = (const float*)d_in[6];
    const float* wo        = (const float*)d_in[7];   // [L,H,D,E]
    const float* ln2_scale = (const float*)d_in[8];
    const float* ln2_bias  = (const float*)d_in[9];
    const float* w1        = (const float*)d_in[10];  // [L,E,M]
    const float* b1        = (const float*)d_in[11];  // [L,M]
    const float* w2        = (const float*)d_in[12];  // [L,M,E]
    const float* b2        = (const float*)d_in[13];  // [L,E]
    const float* lnf_scale = (const float*)d_in[14];  // [E]
    const float* lnf_bias  = (const float*)d_in[15];
    float* out = (float*)d_out;

    static float *px = nullptr, *ph, *pq, *pk, *pv, *pt, *pkv, *pz;
    if (!px) {
        cudaGetSymbolAddress((void**)&px,  g_x);
        cudaGetSymbolAddress((void**)&ph,  g_h);
        cudaGetSymbolAddress((void**)&pq,  g_phiq);
        cudaGetSymbolAddress((void**)&pk,  g_phik);
        cudaGetSymbolAddress((void**)&pv,  g_v);
        cudaGetSymbolAddress((void**)&pt,  g_t);
        cudaGetSymbolAddress((void**)&pkv, g_kv);
        cudaGetSymbolAddress((void**)&pz,  g_z);
    }

    // embedding + positional encoding
    embed_pe_kernel<<<(Nrows * Ez + 255) / 256, 256>>>(inputs, embed, px);

    dim3 gE(Ez / 64, Nrows / 64);     // 512-wide GEMMs
    dim3 gM(Mz / 64, Nrows / 64);     // 2048-wide GEMM
    dim3 gKV(Bz * Hz, KV_SPLITS);
    dim3 gND(Bz * Hz, Sz / 64);

    for (int l = 0; l < Lz; l++) {
        const float* wql = wq + (size_t)l * Ez * Hz * Dz;
        const float* wkl = wk + (size_t)l * Ez * Hz * Dz;
        const float* wvl = wv + (size_t)l * Ez * Hz * Dz;
        const float* wol = wo + (size_t)l * Hz * Dz * Ez;
        const float* w1l = w1 + (size_t)l * Ez * Mz;
        const float* w2l = w2 + (size_t)l * Mz * Ez;

        // LN1
        layernorm_kernel<<<Nrows, 256>>>(px, ph, ln1_scale + l * Ez, ln1_bias + l * Ez);
        // q,k,v projections with phi epilogues
        gemm64<1><<<gE, 256>>>(ph, wql, pq, Ez, Ez, nullptr, nullptr, nullptr);
        gemm64<2><<<gE, 256>>>(ph, wkl, pk, Ez, Ez, nullptr, nullptr, inputs);
        gemm64<0><<<gE, 256>>>(ph, wvl, pv, Ez, Ez, nullptr, nullptr, nullptr);
        // kv / z
        zero_kv_kernel<<<(Bz * Hz * Dz * Dz + 255) / 256, 256>>>(pkv, pz);
        kv_kernel<<<gKV, 256>>>(pk, pv, pkv, pz);
        // num/den -> attention head output (reuse v buffer)
        numden_kernel<<<gND, 256>>>(pq, pkv, pz, pv);
        // output projection + residual
        gemm64<5><<<gE, 256>>>(pv, wol, px, Ez, Ez, nullptr, px, nullptr);
        // LN2
        layernorm_kernel<<<Nrows, 256>>>(px, ph, ln2_scale + l * Ez, ln2_bias + l * Ez);
        // FFN
        gemm64<3><<<gM, 256>>>(ph, w1l, pt, Ez, Mz, b1 + (size_t)l * Mz, nullptr, nullptr);
        gemm64<4><<<gE, 256>>>(pt, w2l, px, Mz, Ez, b2 + (size_t)l * Ez, px, nullptr);
    }

    // final layernorm -> output
    layernorm_kernel<<<Nrows, 256>>>(px, out, lnf_scale, lnf_bias);
}

// round 2
// speedup vs baseline: 1.1797x; 1.1797x over previous
#include <cuda_runtime.h>
#include <cuda_bf16.h>
#include <math.h>

// Problem constants
#define Bz 4
#define Sz 4096
#define Ez 512
#define Hz 8
#define Dz 64
#define Mz 2048
#define Lz 6
#define Nrows (Bz*Sz)          // 16384
#define LN_EPS 1e-6f
#define KEPS 1e-3f

// ---------------- device scratch (no allocations allowed) ----------------
__device__ float g_x[Nrows*Ez];     // residual stream
__device__ float g_h[Nrows*Ez];     // LN output
__device__ float g_phiq[Nrows*Ez];
__device__ float g_phik[Nrows*Ez];
__device__ float g_v[Nrows*Ez];     // v, then reused as attention output
__device__ float g_t[Nrows*Mz];     // FFN mid
__device__ float g_kv[Bz*Hz*Dz*Dz];
__device__ float g_z[Bz*Hz*Dz];

// ---------------- embedding + sinusoidal PE ----------------
__global__ void embed_pe_kernel(const int* __restrict__ inp,
                                const float* __restrict__ emb,
                                float* __restrict__ x) {
    int idx = blockIdx.x * blockDim.x + threadIdx.x;
    if (idx >= Nrows * Ez) return;
    int e = idx & (Ez - 1);
    int n = idx >> 9;           // / Ez
    int s = n & (Sz - 1);
    int tok = inp[n];
    int j = (e >> 1) * 2;
    const float c = -9.210340371976184f / (float)Ez;   // -ln(10000)/E
    float ang = (float)s * expf((float)j * c);
    float pe = (e & 1) ? cosf(ang) : sinf(ang);
    x[idx] = emb[(size_t)tok * Ez + e] + pe;
}

// ---------------- layernorm (one block per row, 256 thr, 2 elems/thr) ----
__device__ __forceinline__ float block_sum(float val, float* red) {
    __syncthreads();
    int t = threadIdx.x;
    #pragma unroll
    for (int o = 16; o; o >>= 1) val += __shfl_down_sync(0xffffffffu, val, o);
    if ((t & 31) == 0) red[t >> 5] = val;
    __syncthreads();
    if (t < 32) {
        float r = (t < 8) ? red[t] : 0.f;
        #pragma unroll
        for (int o = 4; o; o >>= 1) r += __shfl_down_sync(0xffffffffu, r, o);
        if (t == 0) red[0] = r;
    }
    __syncthreads();
    return red[0];
}

__global__ void layernorm_kernel(const float* __restrict__ in,
                                 float* __restrict__ out,
                                 const float* __restrict__ scale,
                                 const float* __restrict__ bias) {
    __shared__ float red[32];
    int n = blockIdx.x;
    int t = threadIdx.x;
    const float* row = in + (size_t)n * Ez;
    float2 v = *(const float2*)&row[t * 2];
    float mu = block_sum(v.x + v.y, red) * (1.f / Ez);
    float dx = v.x - mu, dy = v.y - mu;
    float var = block_sum(dx * dx + dy * dy, red) * (1.f / Ez);
    float rs = rsqrtf(var + LN_EPS);
    float2 o;
    o.x = dx * rs * scale[t * 2 + 0] + bias[t * 2 + 0];
    o.y = dy * rs * scale[t * 2 + 1] + bias[t * 2 + 1];
    *(float2*)&out[(size_t)n * Ez + t * 2] = o;
}

// ---------------- 128x128x16 tiled GEMM, 8x8 per thread --------------------
// C[Nr,NC] = A[Nr,K] @ W[K,NC]
// EPI: 0 plain, 1 relu+eps, 2 (relu+eps)*mask, 3 gelu(x+bias),
//      4 x+bias+resid, 5 x+resid
__device__ __forceinline__ float gelu_tanh(float x) {
    float x3 = x * x * x;
    return 0.5f * x * (1.f + tanhf(0.7978845608028654f * (x + 0.044715f * x3)));
}

template<int EPI>
__global__ void __launch_bounds__(256, 2)
gemm128(const float* __restrict__ A, const float* __restrict__ W,
        float* __restrict__ C, int K, int NC,
        const float* __restrict__ bias,
        const float* __restrict__ resid,
        const int* __restrict__ maskTok) {
    __shared__ float As[16][128];   // [k][row]
    __shared__ float Bs[16][128];   // [k][col]
    int tid = threadIdx.x;
    int tx = tid & 15, ty = tid >> 4;
    int rowBase = blockIdx.y * 128;
    int colBase = blockIdx.x * 128;

    // A-tile load mapping: 128 rows x 16 k = 512 float4; thread handles f4
    // indices tid and tid+256: row = i>>2, kcol = (i&3)*4
    int aRow0 = tid >> 2;             // 0..63
    int aKc   = (tid & 3) * 4;
    // B-tile: 16 k x 128 cols = 512 float4: krow = i>>5, col = (i&31)*4
    int bK0   = tid >> 5;             // 0..7
    int bCol  = (tid & 31) * 4;

    const float* Ag0 = A + (size_t)(rowBase + aRow0) * K + aKc;
    const float* Ag1 = A + (size_t)(rowBase + aRow0 + 64) * K + aKc;
    const float* Bg0 = W + (size_t)bK0 * NC + colBase + bCol;
    const float* Bg1 = W + (size_t)(bK0 + 8) * NC + colBase + bCol;

    float4 pa0 = *(const float4*)Ag0;
    float4 pa1 = *(const float4*)Ag1;
    float4 pb0 = *(const float4*)Bg0;
    float4 pb1 = *(const float4*)Bg1;

    float acc[8][8];
    #pragma unroll
    for (int i = 0; i < 8; i++)
        #pragma unroll
        for (int j = 0; j < 8; j++) acc[i][j] = 0.f;

    for (int k0 = 0; k0 < K; k0 += 16) {
        // commit prefetched tile to smem (A transposed)
        As[aKc + 0][aRow0] = pa0.x;
        As[aKc + 1][aRow0] = pa0.y;
        As[aKc + 2][aRow0] = pa0.z;
        As[aKc + 3][aRow0] = pa0.w;
        As[aKc + 0][aRow0 + 64] = pa1.x;
        As[aKc + 1][aRow0 + 64] = pa1.y;
        As[aKc + 2][aRow0 + 64] = pa1.z;
        As[aKc + 3][aRow0 + 64] = pa1.w;
        *(float4*)&Bs[bK0][bCol]     = pb0;
        *(float4*)&Bs[bK0 + 8][bCol] = pb1;
        __syncthreads();

        // prefetch next tile while computing
        if (k0 + 16 < K) {
            pa0 = *(const float4*)(Ag0 + k0 + 16);
            pa1 = *(const float4*)(Ag1 + k0 + 16);
            pb0 = *(const float4*)(Bg0 + (size_t)(k0 + 16) * NC);
            pb1 = *(const float4*)(Bg1 + (size_t)(k0 + 16) * NC);
        }

        #pragma unroll
        for (int kk = 0; kk < 16; kk++) {
            float a[8], b[8];
            *(float4*)&a[0] = *(const float4*)&As[kk][ty * 8];
            *(float4*)&a[4] = *(const float4*)&As[kk][ty * 8 + 4];
            *(float4*)&b[0] = *(const float4*)&Bs[kk][tx * 8];
            *(float4*)&b[4] = *(const float4*)&Bs[kk][tx * 8 + 4];
            #pragma unroll
            for (int i = 0; i < 8; i++)
                #pragma unroll
                for (int j = 0; j < 8; j++) acc[i][j] = fmaf(a[i], b[j], acc[i][j]);
        }
        __syncthreads();
    }

    #pragma unroll
    for (int i = 0; i < 8; i++) {
        int r = rowBase + ty * 8 + i;
        float m = 1.f;
        if (EPI == 2) m = (maskTok[r] > 0) ? 1.f : 0.f;
        float ov[8];
        #pragma unroll
        for (int j = 0; j < 8; j++) {
            int c = colBase + tx * 8 + j;
            float val = acc[i][j];
            if (EPI == 1) val = fmaxf(val, 0.f) + KEPS;
            if (EPI == 2) val = (fmaxf(val, 0.f) + KEPS) * m;
            if (EPI == 3) val = gelu_tanh(val + bias[c]);
            if (EPI == 4) val = val + bias[c] + resid[(size_t)r * NC + c];
            if (EPI == 5) val = val + resid[(size_t)r * NC + c];
            ov[j] = val;
        }
        *(float4*)&C[(size_t)r * NC + colBase + tx * 8]     = *(float4*)&ov[0];
        *(float4*)&C[(size_t)r * NC + colBase + tx * 8 + 4] = *(float4*)&ov[4];
    }
}

// ---------------- zero kv/z -----------------------------------------------
__global__ void zero_kv_kernel(float* kv, float* z) {
    int i = blockIdx.x * blockDim.x + threadIdx.x;
    if (i < Bz * Hz * Dz * Dz) kv[i] = 0.f;
    if (i < Bz * Hz * Dz) z[i] = 0.f;
}

// ---------------- kv = phik^T @ v (per b,h), z = sum phik ------------------
#define KV_SPLITS 8
__global__ void kv_kernel(const float* __restrict__ phik,
                          const float* __restrict__ v,
                          float* __restrict__ kv, float* __restrict__ z) {
    int bh = blockIdx.x;              // 0..31
    int split = blockIdx.y;           // 0..KV_SPLITS-1
    int b = bh >> 3, h = bh & 7;
    const int CH = Sz / KV_SPLITS;    // 512
    int s0 = split * CH;
    __shared__ float ks[32][64];
    __shared__ float vs[32][64];
    int tid = threadIdx.x;
    int tx = tid & 15, ty = tid >> 4;

    float acc[4][4];
    #pragma unroll
    for (int i = 0; i < 4; i++)
        #pragma unroll
        for (int j = 0; j < 4; j++) acc[i][j] = 0.f;
    float zacc[4] = {0.f, 0.f, 0.f, 0.f};

    for (int c = 0; c < CH; c += 32) {
        #pragma unroll
        for (int r = 0; r < 2; r++) {
            int f4 = tid + r * 256;       // 512 float4s = 32x64 floats
            int row = f4 >> 4;
            int col = (f4 & 15) * 4;
            size_t base = ((size_t)(b * Sz + s0 + c + row)) * Ez + h * 64 + col;
            *(float4*)&ks[row][col] = *(const float4*)&phik[base];
            *(float4*)&vs[row][col] = *(const float4*)&v[base];
        }
        __syncthreads();
        #pragma unroll
        for (int s = 0; s < 32; s++) {
            float a[4], bb[4];
            #pragma unroll
            for (int i = 0; i < 4; i++) { a[i] = ks[s][ty * 4 + i]; bb[i] = vs[s][tx * 4 + i]; }
            #pragma unroll
            for (int i = 0; i < 4; i++)
                #pragma unroll
                for (int j = 0; j < 4; j++) acc[i][j] = fmaf(a[i], bb[j], acc[i][j]);
            if (tx == 0) {
                #pragma unroll
                for (int i = 0; i < 4; i++) zacc[i] += a[i];
            }
        }
        __syncthreads();
    }
    float* kvp = kv + bh * Dz * Dz;
    #pragma unroll
    for (int i = 0; i < 4; i++)
        #pragma unroll
        for (int j = 0; j < 4; j++)
            atomicAdd(&kvp[(ty * 4 + i) * 64 + tx * 4 + j], acc[i][j]);
    if (tx == 0) {
        #pragma unroll
        for (int i = 0; i < 4; i++)
            atomicAdd(&z[bh * 64 + ty * 4 + i], zacc[i]);
    }
}

// ---------------- out = (phiq @ kv) / (phiq . z) ---------------------------
__global__ void numden_kernel(const float* __restrict__ phiq,
                              const float* __restrict__ kv,
                              const float* __restrict__ z,
                              float* __restrict__ out) {
    int bh = blockIdx.x;          // 0..31
    int chunk = blockIdx.y;       // 64 rows each
    int b = bh >> 3, h = bh & 7;
    __shared__ float kvs[64][64];
    __shared__ float zs[64];
    __shared__ float pqs[4][64];
    int tid = threadIdx.x;
    int tx = tid & 63, ty = tid >> 6;

    #pragma unroll
    for (int r = 0; r < 4; r++) {
        int f4 = tid + r * 256;       // 1024 float4s = 64x64
        int row = f4 >> 4;
        int col = (f4 & 15) * 4;
        *(float4*)&kvs[row][col] = *(const float4*)&kv[bh * Dz * Dz + row * 64 + col];
    }
    if (tid < 64) zs[tid] = z[bh * 64 + tid];
    __syncthreads();

    int s0 = chunk * 64;
    for (int it = 0; it < 16; it++) {
        int s = s0 + it * 4 + ty;
        size_t base = ((size_t)(b * Sz + s)) * Ez + h * 64;
        pqs[ty][tx] = phiq[base + tx];
        __syncthreads();
        float num = 0.f, den = 0.f;
        #pragma unroll
        for (int m = 0; m < 64; m++) {
            float p = pqs[ty][m];
            num = fmaf(p, kvs[m][tx], num);
            den = fmaf(p, zs[m], den);
        }
        out[base + tx] = num / den;
        __syncthreads();
    }
}

// ---------------- host side ------------------------------------------------
extern "C" void kernel_launch(void* const* d_in, const int* in_sizes, int n_in,
                              void* d_out, int out_size) {
    const int*   inputs    = (const int*)  d_in[0];   // [B,S]
    const float* embed     = (const float*)d_in[1];   // [V,E]
    const float* ln1_scale = (const float*)d_in[2];   // [L,E]
    const float* ln1_bias  = (const float*)d_in[3];
    const float* wq        = (const float*)d_in[4];   // [L,E,H,D]
    const float* wk        = (const float*)d_in[5];
    const float* wv        = (const float*)d_in[6];
    const float* wo        = (const float*)d_in[7];   // [L,H,D,E]
    const float* ln2_scale = (const float*)d_in[8];
    const float* ln2_bias  = (const float*)d_in[9];
    const float* w1        = (const float*)d_in[10];  // [L,E,M]
    const float* b1        = (const float*)d_in[11];  // [L,M]
    const float* w2        = (const float*)d_in[12];  // [L,M,E]
    const float* b2        = (const float*)d_in[13];  // [L,E]
    const float* lnf_scale = (const float*)d_in[14];  // [E]
    const float* lnf_bias  = (const float*)d_in[15];
    float* out = (float*)d_out;

    static float *px = nullptr, *ph, *pq, *pk, *pv, *pt, *pkv, *pz;
    if (!px) {
        cudaGetSymbolAddress((void**)&px,  g_x);
        cudaGetSymbolAddress((void**)&ph,  g_h);
        cudaGetSymbolAddress((void**)&pq,  g_phiq);
        cudaGetSymbolAddress((void**)&pk,  g_phik);
        cudaGetSymbolAddress((void**)&pv,  g_v);
        cudaGetSymbolAddress((void**)&pt,  g_t);
        cudaGetSymbolAddress((void**)&pkv, g_kv);
        cudaGetSymbolAddress((void**)&pz,  g_z);
    }

    // embedding + positional encoding
    embed_pe_kernel<<<(Nrows * Ez + 255) / 256, 256>>>(inputs, embed, px);

    dim3 gE(Ez / 128, Nrows / 128);   // 512-wide GEMMs: 4 x 128
    dim3 gM(Mz / 128, Nrows / 128);   // 2048-wide GEMM: 16 x 128
    dim3 gKV(Bz * Hz, KV_SPLITS);
    dim3 gND(Bz * Hz, Sz / 64);

    for (int l = 0; l < Lz; l++) {
        const float* wql = wq + (size_t)l * Ez * Hz * Dz;
        const float* wkl = wk + (size_t)l * Ez * Hz * Dz;
        const float* wvl = wv + (size_t)l * Ez * Hz * Dz;
        const float* wol = wo + (size_t)l * Hz * Dz * Ez;
        const float* w1l = w1 + (size_t)l * Ez * Mz;
        const float* w2l = w2 + (size_t)l * Mz * Ez;

        // LN1
        layernorm_kernel<<<Nrows, 256>>>(px, ph, ln1_scale + l * Ez, ln1_bias + l * Ez);
        // q,k,v projections with phi epilogues
        gemm128<1><<<gE, 256>>>(ph, wql, pq, Ez, Ez, nullptr, nullptr, nullptr);
        gemm128<2><<<gE, 256>>>(ph, wkl, pk, Ez, Ez, nullptr, nullptr, inputs);
        gemm128<0><<<gE, 256>>>(ph, wvl, pv, Ez, Ez, nullptr, nullptr, nullptr);
        // kv / z
        zero_kv_kernel<<<(Bz * Hz * Dz * Dz + 255) / 256, 256>>>(pkv, pz);
        kv_kernel<<<gKV, 256>>>(pk, pv, pkv, pz);
        // num/den -> attention head output (reuse v buffer)
        numden_kernel<<<gND, 256>>>(pq, pkv, pz, pv);
        // output projection + residual
        gemm128<5><<<gE, 256>>>(pv, wol, px, Ez, Ez, nullptr, px, nullptr);
        // LN2
        layernorm_kernel<<<Nrows, 256>>>(px, ph, ln2_scale + l * Ez, ln2_bias + l * Ez);
        // FFN
        gemm128<3><<<gM, 256>>>(ph, w1l, pt, Ez, Mz, b1 + (size_t)l * Mz, nullptr, nullptr);
        gemm128<4><<<gE, 256>>>(pt, w2l, px, Mz, Ez, b2 + (size_t)l * Ez, px, nullptr);
    }

    // final layernorm -> output
    layernorm_kernel<<<Nrows, 256>>>(px, out, lnf_scale, lnf_bias);
}

// round 3
// speedup vs baseline: 1.9905x; 1.6872x over previous
#include <cuda_runtime.h>
#include <cuda_bf16.h>
#include <math.h>
#include <stdint.h>

// Problem constants
#define Bz 4
#define Sz 4096
#define Ez 512
#define Hz 8
#define Dz 64
#define Mz 2048
#define Lz 6
#define Nrows (Bz*Sz)          // 16384
#define LN_EPS 1e-6f
#define KEPS 1e-3f

// ---------------- device scratch (no allocations allowed) ----------------
__device__ float g_x[Nrows*Ez];     // residual stream
__device__ float g_h[Nrows*Ez];     // LN output
__device__ float g_phiq[Nrows*Ez];
__device__ float g_phik[Nrows*Ez];
__device__ float g_v[Nrows*Ez];     // v, then reused as attention output
__device__ float g_t[Nrows*Mz];     // FFN mid
__device__ float g_kv[Bz*Hz*Dz*Dz];
__device__ float g_z[Bz*Hz*Dz];

// ---------------- embedding + sinusoidal PE ----------------
__global__ void embed_pe_kernel(const int* __restrict__ inp,
                                const float* __restrict__ emb,
                                float* __restrict__ x) {
    int idx = blockIdx.x * blockDim.x + threadIdx.x;
    if (idx >= Nrows * Ez) return;
    int e = idx & (Ez - 1);
    int n = idx >> 9;           // / Ez
    int s = n & (Sz - 1);
    int tok = inp[n];
    int j = (e >> 1) * 2;
    const float c = -9.210340371976184f / (float)Ez;   // -ln(10000)/E
    float ang = (float)s * expf((float)j * c);
    float pe = (e & 1) ? cosf(ang) : sinf(ang);
    x[idx] = emb[(size_t)tok * Ez + e] + pe;
}

// ---------------- layernorm (one block per row, 256 thr, 2 elems/thr) ----
__device__ __forceinline__ float block_sum(float val, float* red) {
    __syncthreads();
    int t = threadIdx.x;
    #pragma unroll
    for (int o = 16; o; o >>= 1) val += __shfl_down_sync(0xffffffffu, val, o);
    if ((t & 31) == 0) red[t >> 5] = val;
    __syncthreads();
    if (t < 32) {
        float r = (t < 8) ? red[t] : 0.f;
        #pragma unroll
        for (int o = 4; o; o >>= 1) r += __shfl_down_sync(0xffffffffu, r, o);
        if (t == 0) red[0] = r;
    }
    __syncthreads();
    return red[0];
}

__global__ void layernorm_kernel(const float* __restrict__ in,
                                 float* __restrict__ out,
                                 const float* __restrict__ scale,
                                 const float* __restrict__ bias) {
    __shared__ float red[32];
    int n = blockIdx.x;
    int t = threadIdx.x;
    const float* row = in + (size_t)n * Ez;
    float2 v = *(const float2*)&row[t * 2];
    float mu = block_sum(v.x + v.y, red) * (1.f / Ez);
    float dx = v.x - mu, dy = v.y - mu;
    float var = block_sum(dx * dx + dy * dy, red) * (1.f / Ez);
    float rs = rsqrtf(var + LN_EPS);
    float2 o;
    o.x = dx * rs * scale[t * 2 + 0] + bias[t * 2 + 0];
    o.y = dy * rs * scale[t * 2 + 1] + bias[t * 2 + 1];
    *(float2*)&out[(size_t)n * Ez + t * 2] = o;
}

// ---------------- tensor-core GEMM (bf16x3 split, fp32 accum) --------------
// C[Nr,NC] = A[Nr,K] @ W[K,NC]
// EPI: 0 plain, 1 relu+eps, 2 (relu+eps)*mask, 3 gelu(x+bias),
//      4 x+bias+resid, 5 x+resid
__device__ __forceinline__ float gelu_tanh(float x) {
    float x3 = x * x * x;
    return 0.5f * x * (1.f + tanhf(0.7978845608028654f * (x + 0.044715f * x3)));
}

__device__ __forceinline__ void mma_bf16(float* c, uint4 a, uint2 b) {
    asm volatile(
        "mma.sync.aligned.m16n8k16.row.col.f32.bf16.bf16.f32 "
        "{%0,%1,%2,%3}, {%4,%5,%6,%7}, {%8,%9}, {%0,%1,%2,%3};"
        : "+f"(c[0]), "+f"(c[1]), "+f"(c[2]), "+f"(c[3])
        : "r"(a.x), "r"(a.y), "r"(a.z), "r"(a.w), "r"(b.x), "r"(b.y));
}

// split x into hi/lo bf16, pack pairs (x0 -> low half)
__device__ __forceinline__ void split_pack(float x0, float x1,
                                           uint32_t& hi, uint32_t& lo) {
    __nv_bfloat162 h = __floats2bfloat162_rn(x0, x1);
    float r0 = x0 - __bfloat162float(h.x);
    float r1 = x1 - __bfloat162float(h.y);
    __nv_bfloat162 l = __floats2bfloat162_rn(r0, r1);
    hi = *reinterpret_cast<uint32_t*>(&h);
    lo = *reinterpret_cast<uint32_t*>(&l);
}

// smem layout (uint32 units), per stage (stride 8192 = 32KB):
//   Ahi @0 (2048), Alo @2048, Bhi @4096, Blo @6144
// A block (mb 0..7, kb 0..1): idx (mb*2+kb)*128 + lane*4  -> one uint4 = frag a0..a3
// B block (kb 0..1, nb 0..15): 4096 + (kb*16+nb)*64 + lane*2 -> uint2 = b0,b1
template<int EPI>
__global__ void gemm_tc(const float* __restrict__ A, const float* __restrict__ W,
                        float* __restrict__ C, int K, int NC,
                        const float* __restrict__ bias,
                        const float* __restrict__ resid,
                        const int* __restrict__ maskTok) {
    extern __shared__ uint32_t sm[];
    const int tid = threadIdx.x;
    const int lane = tid & 31, warp = tid >> 5;
    const int wm = warp & 1, wn = warp >> 1;
    const int g = lane >> 2, tq = lane & 3;
    const long rowBase = (long)blockIdx.y * 128;
    const int colBase = blockIdx.x * 128;

    // ---- loader task decode (A: 2 tasks, B: 4 tasks per thread) ----
    const float* aP0[2]; const float* aP1[2]; int aOff[2]; int aSts[2];
    #pragma unroll
    for (int i = 0; i < 2; i++) {
        int task = tid + i * 256;
        int b = task >> 5, l = task & 31;
        int mb = b >> 1, kb = b & 1;
        int lg = l >> 2, lt = l & 3;
        aP0[i] = A + (size_t)(rowBase + mb * 16 + lg) * K;
        aP1[i] = A + (size_t)(rowBase + mb * 16 + lg + 8) * K;
        aOff[i] = kb * 16 + 2 * lt;
        aSts[i] = b * 128 + l * 4;
    }
    const float* bP[4]; int bSts[4];
    #pragma unroll
    for (int j = 0; j < 4; j++) {
        int task = tid + j * 256;
        int bb = task >> 5, l = task & 31;
        int kb = bb >> 4, nb = bb & 15;
        int lg = l >> 2, lt = l & 3;
        bP[j] = W + (size_t)(kb * 16 + 2 * lt) * NC + colBase + nb * 8 + lg;
        bSts[j] = bb * 64 + l * 2;
    }

    float2 fa[2][4];
    float  fb[4][4];

    float acc[4][4][4];
    #pragma unroll
    for (int mt = 0; mt < 4; mt++)
        #pragma unroll
        for (int nt = 0; nt < 4; nt++)
            #pragma unroll
            for (int r = 0; r < 4; r++) acc[mt][nt][r] = 0.f;

    const int NS = K >> 5;

    // ---- prologue: load + store stage 0 ----
    #pragma unroll
    for (int i = 0; i < 2; i++) {
        const float* p0 = aP0[i] + aOff[i];
        const float* p1 = aP1[i] + aOff[i];
        fa[i][0] = *(const float2*)p0;
        fa[i][1] = *(const float2*)p1;
        fa[i][2] = *(const float2*)(p0 + 8);
        fa[i][3] = *(const float2*)(p1 + 8);
    }
    #pragma unroll
    for (int j = 0; j < 4; j++) {
        const float* p = bP[j];
        fb[j][0] = p[0]; fb[j][1] = p[NC];
        fb[j][2] = p[(size_t)8 * NC]; fb[j][3] = p[(size_t)9 * NC];
    }
    {
        #pragma unroll
        for (int i = 0; i < 2; i++) {
            uint4 hi, lo;
            split_pack(fa[i][0].x, fa[i][0].y, hi.x, lo.x);
            split_pack(fa[i][1].x, fa[i][1].y, hi.y, lo.y);
            split_pack(fa[i][2].x, fa[i][2].y, hi.z, lo.z);
            split_pack(fa[i][3].x, fa[i][3].y, hi.w, lo.w);
            *(uint4*)&sm[aSts[i]] = hi;
            *(uint4*)&sm[2048 + aSts[i]] = lo;
        }
        #pragma unroll
        for (int j = 0; j < 4; j++) {
            uint2 h2, l2;
            split_pack(fb[j][0], fb[j][1], h2.x, l2.x);
            split_pack(fb[j][2], fb[j][3], h2.y, l2.y);
            *(uint2*)&sm[4096 + bSts[j]] = h2;
            *(uint2*)&sm[6144 + bSts[j]] = l2;
        }
    }
    __syncthreads();

    for (int s = 0; s < NS; s++) {
        int k1 = (s + 1) * 32;
        if (s + 1 < NS) {
            #pragma unroll
            for (int i = 0; i < 2; i++) {
                const float* p0 = aP0[i] + k1 + aOff[i];
                const float* p1 = aP1[i] + k1 + aOff[i];
                fa[i][0] = *(const float2*)p0;
                fa[i][1] = *(const float2*)p1;
                fa[i][2] = *(const float2*)(p0 + 8);
                fa[i][3] = *(const float2*)(p1 + 8);
            }
            #pragma unroll
            for (int j = 0; j < 4; j++) {
                const float* p = bP[j] + (size_t)k1 * NC;
                fb[j][0] = p[0]; fb[j][1] = p[NC];
                fb[j][2] = p[(size_t)8 * NC]; fb[j][3] = p[(size_t)9 * NC];
            }
        }
        int base = (s & 1) * 8192;
        #pragma unroll
        for (int kb = 0; kb < 2; kb++) {
            uint4 Ah[4], Al[4]; uint2 Bh[4], Bl[4];
            #pragma unroll
            for (int mt = 0; mt < 4; mt++) {
                int blk = base + ((wm * 4 + mt) * 2 + kb) * 128 + lane * 4;
                Ah[mt] = *(uint4*)&sm[blk];
                Al[mt] = *(uint4*)&sm[blk + 2048];
            }
            #pragma unroll
            for (int nt = 0; nt < 4; nt++) {
                int bo = base + 4096 + (kb * 16 + wn * 4 + nt) * 64 + lane * 2;
                Bh[nt] = *(uint2*)&sm[bo];
                Bl[nt] = *(uint2*)&sm[bo + 2048];
            }
            #pragma unroll
            for (int mt = 0; mt < 4; mt++)
                #pragma unroll
                for (int nt = 0; nt < 4; nt++)
                    mma_bf16(acc[mt][nt], Ah[mt], Bh[nt]);
            #pragma unroll
            for (int mt = 0; mt < 4; mt++)
                #pragma unroll
                for (int nt = 0; nt < 4; nt++)
                    mma_bf16(acc[mt][nt], Ah[mt], Bl[nt]);
            #pragma unroll
            for (int mt = 0; mt < 4; mt++)
                #pragma unroll
                for (int nt = 0; nt < 4; nt++)
                    mma_bf16(acc[mt][nt], Al[mt], Bh[nt]);
        }
        if (s + 1 < NS) {
            int nbase = ((s + 1) & 1) * 8192;
            #pragma unroll
            for (int i = 0; i < 2; i++) {
                uint4 hi, lo;
                split_pack(fa[i][0].x, fa[i][0].y, hi.x, lo.x);
                split_pack(fa[i][1].x, fa[i][1].y, hi.y, lo.y);
                split_pack(fa[i][2].x, fa[i][2].y, hi.z, lo.z);
                split_pack(fa[i][3].x, fa[i][3].y, hi.w, lo.w);
                *(uint4*)&sm[nbase + aSts[i]] = hi;
                *(uint4*)&sm[nbase + 2048 + aSts[i]] = lo;
            }
            #pragma unroll
            for (int j = 0; j < 4; j++) {
                uint2 h2, l2;
                split_pack(fb[j][0], fb[j][1], h2.x, l2.x);
                split_pack(fb[j][2], fb[j][3], h2.y, l2.y);
                *(uint2*)&sm[nbase + 4096 + bSts[j]] = h2;
                *(uint2*)&sm[nbase + 6144 + bSts[j]] = l2;
            }
        }
        __syncthreads();
    }

    // ---- epilogue ----
    #pragma unroll
    for (int mt = 0; mt < 4; mt++) {
        long r0 = rowBase + wm * 64 + mt * 16 + g;
        long r1 = r0 + 8;
        float m0 = 1.f, m1 = 1.f;
        if (EPI == 2) {
            m0 = (maskTok[r0] > 0) ? 1.f : 0.f;
            m1 = (maskTok[r1] > 0) ? 1.f : 0.f;
        }
        #pragma unroll
        for (int nt = 0; nt < 4; nt++) {
            int c = colBase + wn * 32 + nt * 8 + 2 * tq;
            float v0 = acc[mt][nt][0], v1 = acc[mt][nt][1];
            float v2 = acc[mt][nt][2], v3 = acc[mt][nt][3];
            if (EPI == 1) {
                v0 = fmaxf(v0, 0.f) + KEPS; v1 = fmaxf(v1, 0.f) + KEPS;
                v2 = fmaxf(v2, 0.f) + KEPS; v3 = fmaxf(v3, 0.f) + KEPS;
            }
            if (EPI == 2) {
                v0 = (fmaxf(v0, 0.f) + KEPS) * m0; v1 = (fmaxf(v1, 0.f) + KEPS) * m0;
                v2 = (fmaxf(v2, 0.f) + KEPS) * m1; v3 = (fmaxf(v3, 0.f) + KEPS) * m1;
            }
            if (EPI == 3) {
                float b0 = bias[c], b1 = bias[c + 1];
                v0 = gelu_tanh(v0 + b0); v1 = gelu_tanh(v1 + b1);
                v2 = gelu_tanh(v2 + b0); v3 = gelu_tanh(v3 + b1);
            }
            if (EPI == 4) {
                float b0 = bias[c], b1 = bias[c + 1];
                v0 += b0 + resid[(size_t)r0 * NC + c];
                v1 += b1 + resid[(size_t)r0 * NC + c + 1];
                v2 += b0 + resid[(size_t)r1 * NC + c];
                v3 += b1 + resid[(size_t)r1 * NC + c + 1];
            }
            if (EPI == 5) {
                v0 += resid[(size_t)r0 * NC + c];
                v1 += resid[(size_t)r0 * NC + c + 1];
                v2 += resid[(size_t)r1 * NC + c];
                v3 += resid[(size_t)r1 * NC + c + 1];
            }
            float2 o0 = {v0, v1}, o1 = {v2, v3};
            *(float2*)&C[(size_t)r0 * NC + c] = o0;
            *(float2*)&C[(size_t)r1 * NC + c] = o1;
        }
    }
}

// ---------------- zero kv/z -----------------------------------------------
__global__ void zero_kv_kernel(float* kv, float* z) {
    int i = blockIdx.x * blockDim.x + threadIdx.x;
    if (i < Bz * Hz * Dz * Dz) kv[i] = 0.f;
    if (i < Bz * Hz * Dz) z[i] = 0.f;
}

// ---------------- kv = phik^T @ v (per b,h), z = sum phik ------------------
#define KV_SPLITS 8
__global__ void kv_kernel(const float* __restrict__ phik,
                          const float* __restrict__ v,
                          float* __restrict__ kv, float* __restrict__ z) {
    int bh = blockIdx.x;              // 0..31
    int split = blockIdx.y;           // 0..KV_SPLITS-1
    int b = bh >> 3, h = bh & 7;
    const int CH = Sz / KV_SPLITS;    // 512
    int s0 = split * CH;
    __shared__ float ks[32][64];
    __shared__ float vs[32][64];
    int tid = threadIdx.x;
    int tx = tid & 15, ty = tid >> 4;

    float acc[4][4];
    #pragma unroll
    for (int i = 0; i < 4; i++)
        #pragma unroll
        for (int j = 0; j < 4; j++) acc[i][j] = 0.f;
    float zacc[4] = {0.f, 0.f, 0.f, 0.f};

    for (int c = 0; c < CH; c += 32) {
        #pragma unroll
        for (int r = 0; r < 2; r++) {
            int f4 = tid + r * 256;       // 512 float4s = 32x64 floats
            int row = f4 >> 4;
            int col = (f4 & 15) * 4;
            size_t base = ((size_t)(b * Sz + s0 + c + row)) * Ez + h * 64 + col;
            *(float4*)&ks[row][col] = *(const float4*)&phik[base];
            *(float4*)&vs[row][col] = *(const float4*)&v[base];
        }
        __syncthreads();
        #pragma unroll
        for (int s = 0; s < 32; s++) {
            float a[4], bb[4];
            #pragma unroll
            for (int i = 0; i < 4; i++) { a[i] = ks[s][ty * 4 + i]; bb[i] = vs[s][tx * 4 + i]; }
            #pragma unroll
            for (int i = 0; i < 4; i++)
                #pragma unroll
                for (int j = 0; j < 4; j++) acc[i][j] = fmaf(a[i], bb[j], acc[i][j]);
            if (tx == 0) {
                #pragma unroll
                for (int i = 0; i < 4; i++) zacc[i] += a[i];
            }
        }
        __syncthreads();
    }
    float* kvp = kv + bh * Dz * Dz;
    #pragma unroll
    for (int i = 0; i < 4; i++)
        #pragma unroll
        for (int j = 0; j < 4; j++)
            atomicAdd(&kvp[(ty * 4 + i) * 64 + tx * 4 + j], acc[i][j]);
    if (tx == 0) {
        #pragma unroll
        for (int i = 0; i < 4; i++)
            atomicAdd(&z[bh * 64 + ty * 4 + i], zacc[i]);
    }
}

// ---------------- out = (phiq @ kv) / (phiq . z) ---------------------------
__global__ void numden_kernel(const float* __restrict__ phiq,
                              const float* __restrict__ kv,
                              const float* __restrict__ z,
                              float* __restrict__ out) {
    int bh = blockIdx.x;          // 0..31
    int chunk = blockIdx.y;       // 64 rows each
    int b = bh >> 3, h = bh & 7;
    __shared__ float kvs[64][64];
    __shared__ float zs[64];
    __shared__ float pqs[4][64];
    int tid = threadIdx.x;
    int tx = tid & 63, ty = tid >> 6;

    #pragma unroll
    for (int r = 0; r < 4; r++) {
        int f4 = tid + r * 256;       // 1024 float4s = 64x64
        int row = f4 >> 4;
        int col = (f4 & 15) * 4;
        *(float4*)&kvs[row][col] = *(const float4*)&kv[bh * Dz * Dz + row * 64 + col];
    }
    if (tid < 64) zs[tid] = z[bh * 64 + tid];
    __syncthreads();

    int s0 = chunk * 64;
    for (int it = 0; it < 16; it++) {
        int s = s0 + it * 4 + ty;
        size_t base = ((size_t)(b * Sz + s)) * Ez + h * 64;
        pqs[ty][tx] = phiq[base + tx];
        __syncthreads();
        float num = 0.f, den = 0.f;
        #pragma unroll
        for (int m = 0; m < 64; m++) {
            float p = pqs[ty][m];
            num = fmaf(p, kvs[m][tx], num);
            den = fmaf(p, zs[m], den);
        }
        out[base + tx] = num / den;
        __syncthreads();
    }
}

// ---------------- host side ------------------------------------------------
#define SMEM_BYTES 65536

extern "C" void kernel_launch(void* const* d_in, const int* in_sizes, int n_in,
                              void* d_out, int out_size) {
    const int*   inputs    = (const int*)  d_in[0];   // [B,S]
    const float* embed     = (const float*)d_in[1];   // [V,E]
    const float* ln1_scale = (const float*)d_in[2];   // [L,E]
    const float* ln1_bias  = (const float*)d_in[3];
    const float* wq        = (const float*)d_in[4];   // [L,E,H,D]
    const float* wk        = (const float*)d_in[5];
    const float* wv        = (const float*)d_in[6];
    const float* wo        = (const float*)d_in[7];   // [L,H,D,E]
    const float* ln2_scale = (const float*)d_in[8];
    const float* ln2_bias  = (const float*)d_in[9];
    const float* w1        = (const float*)d_in[10];  // [L,E,M]
    const float* b1        = (const float*)d_in[11];  // [L,M]
    const float* w2        = (const float*)d_in[12];  // [L,M,E]
    const float* b2        = (const float*)d_in[13];  // [L,E]
    const float* lnf_scale = (const float*)d_in[14];  // [E]
    const float* lnf_bias  = (const float*)d_in[15];
    float* out = (float*)d_out;

    static float *px = nullptr, *ph, *pq, *pk, *pv, *pt, *pkv, *pz;
    if (!px) {
        cudaGetSymbolAddress((void**)&px,  g_x);
        cudaGetSymbolAddress((void**)&ph,  g_h);
        cudaGetSymbolAddress((void**)&pq,  g_phiq);
        cudaGetSymbolAddress((void**)&pk,  g_phik);
        cudaGetSymbolAddress((void**)&pv,  g_v);
        cudaGetSymbolAddress((void**)&pt,  g_t);
        cudaGetSymbolAddress((void**)&pkv, g_kv);
        cudaGetSymbolAddress((void**)&pz,  g_z);
        cudaFuncSetAttribute(gemm_tc<0>, cudaFuncAttributeMaxDynamicSharedMemorySize, SMEM_BYTES);
        cudaFuncSetAttribute(gemm_tc<1>, cudaFuncAttributeMaxDynamicSharedMemorySize, SMEM_BYTES);
        cudaFuncSetAttribute(gemm_tc<2>, cudaFuncAttributeMaxDynamicSharedMemorySize, SMEM_BYTES);
        cudaFuncSetAttribute(gemm_tc<3>, cudaFuncAttributeMaxDynamicSharedMemorySize, SMEM_BYTES);
        cudaFuncSetAttribute(gemm_tc<4>, cudaFuncAttributeMaxDynamicSharedMemorySize, SMEM_BYTES);
        cudaFuncSetAttribute(gemm_tc<5>, cudaFuncAttributeMaxDynamicSharedMemorySize, SMEM_BYTES);
    }

    // embedding + positional encoding
    embed_pe_kernel<<<(Nrows * Ez + 255) / 256, 256>>>(inputs, embed, px);

    dim3 gE(Ez / 128, Nrows / 128);   // 512-wide GEMMs: 4 x 128
    dim3 gM(Mz / 128, Nrows / 128);   // 2048-wide GEMM: 16 x 128
    dim3 gKV(Bz * Hz, KV_SPLITS);
    dim3 gND(Bz * Hz, Sz / 64);

    for (int l = 0; l < Lz; l++) {
        const float* wql = wq + (size_t)l * Ez * Hz * Dz;
        const float* wkl = wk + (size_t)l * Ez * Hz * Dz;
        const float* wvl = wv + (size_t)l * Ez * Hz * Dz;
        const float* wol = wo + (size_t)l * Hz * Dz * Ez;
        const float* w1l = w1 + (size_t)l * Ez * Mz;
        const float* w2l = w2 + (size_t)l * Mz * Ez;

        // LN1
        layernorm_kernel<<<Nrows, 256>>>(px, ph, ln1_scale + l * Ez, ln1_bias + l * Ez);
        // q,k,v projections with phi epilogues
        gemm_tc<1><<<gE, 256, SMEM_BYTES>>>(ph, wql, pq, Ez, Ez, nullptr, nullptr, nullptr);
        gemm_tc<2><<<gE, 256, SMEM_BYTES>>>(ph, wkl, pk, Ez, Ez, nullptr, nullptr, inputs);
        gemm_tc<0><<<gE, 256, SMEM_BYTES>>>(ph, wvl, pv, Ez, Ez, nullptr, nullptr, nullptr);
        // kv / z
        zero_kv_kernel<<<(Bz * Hz * Dz * Dz + 255) / 256, 256>>>(pkv, pz);
        kv_kernel<<<gKV, 256>>>(pk, pv, pkv, pz);
        // num/den -> attention head output (reuse v buffer)
        numden_kernel<<<gND, 256>>>(pq, pkv, pz, pv);
        // output projection + residual
        gemm_tc<5><<<gE, 256, SMEM_BYTES>>>(pv, wol, px, Ez, Ez, nullptr, px, nullptr);
        // LN2
        layernorm_kernel<<<Nrows, 256>>>(px, ph, ln2_scale + l * Ez, ln2_bias + l * Ez);
        // FFN
        gemm_tc<3><<<gM, 256, SMEM_BYTES>>>(ph, w1l, pt, Ez, Mz, b1 + (size_t)l * Mz, nullptr, nullptr);
        gemm_tc<4><<<gE, 256, SMEM_BYTES>>>(pt, w2l, px, Mz, Ez, b2 + (size_t)l * Ez, px, nullptr);
    }

    // final layernorm -> output
    layernorm_kernel<<<Nrows, 256>>>(px, out, lnf_scale, lnf_bias);
}

// round 4
// speedup vs baseline: 3.0548x; 1.5347x over previous
#include <cuda_runtime.h>
#include <cuda_bf16.h>
#include <math.h>
#include <stdint.h>

// Problem constants
#define Bz 4
#define Sz 4096
#define Ez 512
#define Hz 8
#define Dz 64
#define Mz 2048
#define Lz 6
#define Nrows (Bz*Sz)          // 16384
#define LN_EPS 1e-6f
#define KEPS 1e-3f

// ---------------- device scratch ----------------
__device__ float g_x[Nrows*Ez];                 // residual stream
__device__ float g_phiq[Nrows*Ez];
__device__ float g_phik[Nrows*Ez];
__device__ float g_v[Nrows*Ez];
__device__ float g_kv[Bz*Hz*Dz*Dz];
__device__ float g_z[Bz*Hz*Dz];
// split-permuted activation buffers (uint32 = packed bf16x2)
__device__ __align__(16) uint32_t g_hAhi[Nrows*256];
__device__ __align__(16) uint32_t g_hAlo[Nrows*256];
__device__ __align__(16) uint32_t g_ndhi[Nrows*256];
__device__ __align__(16) uint32_t g_ndlo[Nrows*256];
__device__ __align__(16) uint32_t g_pthi[Nrows*1024];
__device__ __align__(16) uint32_t g_ptlo[Nrows*1024];
// split-permuted weights: [qkv,o: 6*131072 each][w1,w2: 6*524288 each]
#define OQ  0
#define OK_ 786432
#define OV  1572864
#define OO  2359296
#define O1  3145728
#define O2  6291456
#define WTOT 9437184
__device__ __align__(16) uint32_t g_whi[WTOT];
__device__ __align__(16) uint32_t g_wlo[WTOT];

// ---------------- helpers ----------------
__device__ __forceinline__ void split_pack(float x0, float x1,
                                           uint32_t& hi, uint32_t& lo) {
    __nv_bfloat162 h = __floats2bfloat162_rn(x0, x1);
    float r0 = x0 - __bfloat162float(h.x);
    float r1 = x1 - __bfloat162float(h.y);
    __nv_bfloat162 l = __floats2bfloat162_rn(r0, r1);
    hi = *reinterpret_cast<uint32_t*>(&h);
    lo = *reinterpret_cast<uint32_t*>(&l);
}

__device__ __forceinline__ void mma_bf16(float* c, uint4 a, uint2 b) {
    asm volatile(
        "mma.sync.aligned.m16n8k16.row.col.f32.bf16.bf16.f32 "
        "{%0,%1,%2,%3}, {%4,%5,%6,%7}, {%8,%9}, {%0,%1,%2,%3};"
        : "+f"(c[0]), "+f"(c[1]), "+f"(c[2]), "+f"(c[3])
        : "r"(a.x), "r"(a.y), "r"(a.z), "r"(a.w), "r"(b.x), "r"(b.y));
}

__device__ __forceinline__ float warp_sum(float v) {
    #pragma unroll
    for (int o = 16; o; o >>= 1) v += __shfl_xor_sync(0xffffffffu, v, o);
    return v;
}

__device__ __forceinline__ float gelu_tanh(float x) {
    float x3 = x * x * x;
    return 0.5f * x * (1.f + tanhf(0.7978845608028654f * (x + 0.044715f * x3)));
}

__device__ __forceinline__ void cp16(uint32_t dst, const void* src) {
    asm volatile("cp.async.cg.shared.global [%0], [%1], 16;\n" :: "r"(dst), "l"(src));
}
__device__ __forceinline__ void cp_commit() {
    asm volatile("cp.async.commit_group;\n");
}
__device__ __forceinline__ void cp_wait1() {
    asm volatile("cp.async.wait_group 1;\n");
}

// ---------------- weight split pre-pass ----------------
// W [K][NC] fp32 -> perm layout: [colTile cb][stage][2048]:
//   uint32 at (kbS*16+nb)*64 + (g*4+tq)*2 + h = pack(W[k][c], W[k+1][c])
//   where c = cb*128+nb*8+g, k = stage*32 + kbS*16 + 2tq + 8h
__global__ void split_w(const float* __restrict__ W,
                        uint32_t* __restrict__ hi, uint32_t* __restrict__ lo,
                        int K, int NC, size_t wStrideL, size_t oStrideL) {
    int l = blockIdx.z;
    const float* Wl = W + (size_t)l * wStrideL;
    uint32_t* hiL = hi + (size_t)l * oStrideL;
    uint32_t* loL = lo + (size_t)l * oStrideL;
    int c = blockIdx.x * 256 + threadIdx.x;
    int kb = blockIdx.y;                 // 0..K/16-1
    int cb = c >> 7, nb = (c >> 3) & 15, g = c & 7;
    int stage = kb >> 1, kbS = kb & 1;
    uint32_t h8[8], l8[8];
    #pragma unroll
    for (int o = 0; o < 8; o++) {
        int tq = o >> 1, hb = o & 1;
        int k = kb * 16 + 2 * tq + 8 * hb;
        float x0 = Wl[(size_t)k * NC + c];
        float x1 = Wl[(size_t)(k + 1) * NC + c];
        split_pack(x0, x1, h8[o], l8[o]);
    }
    size_t I = ((size_t)(cb * (K >> 5) + stage)) * 2048 + (kbS * 16 + nb) * 64 + g * 8;
    *(uint4*)&hiL[I]     = *(uint4*)&h8[0];
    *(uint4*)&hiL[I + 4] = *(uint4*)&h8[4];
    *(uint4*)&loL[I]     = *(uint4*)&l8[0];
    *(uint4*)&loL[I + 4] = *(uint4*)&l8[4];
}

// ---------------- embedding + sinusoidal PE ----------------
__global__ void embed_pe_kernel(const int* __restrict__ inp,
                                const float* __restrict__ emb,
                                float* __restrict__ x) {
    int idx = blockIdx.x * blockDim.x + threadIdx.x;
    if (idx >= Nrows * Ez) return;
    int e = idx & (Ez - 1);
    int n = idx >> 9;
    int s = n & (Sz - 1);
    int tok = inp[n];
    int j = (e >> 1) * 2;
    const float c = -9.210340371976184f / (float)Ez;
    float ang = (float)s * expf((float)j * c);
    float pe = (e & 1) ? cosf(ang) : sinf(ang);
    x[idx] = emb[(size_t)tok * Ez + e] + pe;
}

// ---------------- layernorm -> fp32 (final only) ----------------
__device__ __forceinline__ float block_sum(float val, float* red) {
    __syncthreads();
    int t = threadIdx.x;
    #pragma unroll
    for (int o = 16; o; o >>= 1) val += __shfl_down_sync(0xffffffffu, val, o);
    if ((t & 31) == 0) red[t >> 5] = val;
    __syncthreads();
    if (t < 32) {
        float r = (t < 8) ? red[t] : 0.f;
        #pragma unroll
        for (int o = 4; o; o >>= 1) r += __shfl_down_sync(0xffffffffu, r, o);
        if (t == 0) red[0] = r;
    }
    __syncthreads();
    return red[0];
}

__global__ void layernorm_kernel(const float* __restrict__ in,
                                 float* __restrict__ out,
                                 const float* __restrict__ scale,
                                 const float* __restrict__ bias) {
    __shared__ float red[32];
    int n = blockIdx.x;
    int t = threadIdx.x;
    const float* row = in + (size_t)n * Ez;
    float2 v = *(const float2*)&row[t * 2];
    float mu = block_sum(v.x + v.y, red) * (1.f / Ez);
    float dx = v.x - mu, dy = v.y - mu;
    float var = block_sum(dx * dx + dy * dy, red) * (1.f / Ez);
    float rs = rsqrtf(var + LN_EPS);
    float2 o;
    o.x = dx * rs * scale[t * 2 + 0] + bias[t * 2 + 0];
    o.y = dy * rs * scale[t * 2 + 1] + bias[t * 2 + 1];
    *(float2*)&out[(size_t)n * Ez + t * 2] = o;
}

// ---------------- layernorm -> split-permuted output ----------------
// block = 256 threads, 16 rows. pitch E=512 -> 16 stages.
__global__ void layernorm_split(const float* __restrict__ in,
                                uint32_t* __restrict__ outHi,
                                uint32_t* __restrict__ outLo,
                                const float* __restrict__ scale,
                                const float* __restrict__ bias) {
    __shared__ float nrm[16][516];
    int tid = threadIdx.x;
    int warp = tid >> 5, lane = tid & 31;
    long n0 = (long)blockIdx.x * 16;

    #pragma unroll
    for (int rr = 0; rr < 2; rr++) {
        int r = warp * 2 + rr;
        const float* row = in + (n0 + r) * Ez;
        float4 v[4];
        float s = 0.f;
        #pragma unroll
        for (int q = 0; q < 4; q++) {
            v[q] = *(const float4*)&row[lane * 4 + q * 128];
            s += v[q].x + v[q].y + v[q].z + v[q].w;
        }
        float mu = warp_sum(s) * (1.f / Ez);
        float vr = 0.f;
        #pragma unroll
        for (int q = 0; q < 4; q++) {
            float a = v[q].x - mu, b = v[q].y - mu, c = v[q].z - mu, d = v[q].w - mu;
            vr += a * a + b * b + c * c + d * d;
        }
        float rs = rsqrtf(warp_sum(vr) * (1.f / Ez) + LN_EPS);
        #pragma unroll
        for (int q = 0; q < 4; q++) {
            int c = lane * 4 + q * 128;
            float4 sc = *(const float4*)&scale[c];
            float4 bi = *(const float4*)&bias[c];
            float4 o;
            o.x = (v[q].x - mu) * rs * sc.x + bi.x;
            o.y = (v[q].y - mu) * rs * sc.y + bi.y;
            o.z = (v[q].z - mu) * rs * sc.z + bi.z;
            o.w = (v[q].w - mu) * rs * sc.w + bi.w;
            *(float4*)&nrm[r][c] = o;
        }
    }
    __syncthreads();

    // write phase: thread (stage, kb, g) writes 16 contiguous uint32
    int g = tid & 7, kb = (tid >> 3) & 1, stage = tid >> 4;
    uint32_t hi[16], lo[16];
    #pragma unroll
    for (int o = 0; o < 16; o++) {
        int tq = o >> 2, kbit = (o >> 1) & 1, rbit = o & 1;
        int c = stage * 32 + kb * 16 + 2 * tq + 8 * kbit;
        int rl = g + 8 * rbit;
        split_pack(nrm[rl][c], nrm[rl][c + 1], hi[o], lo[o]);
    }
    size_t I = ((size_t)((blockIdx.x >> 3) * 16 + stage)) * 2048
             + ((blockIdx.x & 7) * 2 + kb) * 128 + g * 16;
    *(uint4*)&outHi[I]      = *(uint4*)&hi[0];
    *(uint4*)&outHi[I + 4]  = *(uint4*)&hi[4];
    *(uint4*)&outHi[I + 8]  = *(uint4*)&hi[8];
    *(uint4*)&outHi[I + 12] = *(uint4*)&hi[12];
    *(uint4*)&outLo[I]      = *(uint4*)&lo[0];
    *(uint4*)&outLo[I + 4]  = *(uint4*)&lo[4];
    *(uint4*)&outLo[I + 8]  = *(uint4*)&lo[8];
    *(uint4*)&outLo[I + 12] = *(uint4*)&lo[12];
}

// ---------------- tensor-core GEMM (pre-split, cp.async pipeline) ----------
// EPI: 0 plain, 1 relu+eps, 2 (relu+eps)*mask, 3 gelu(x+bias),
//      4 x+bias+resid, 5 x+resid
// OUT: 0 = fp32 C, 1 = split-permuted (outHi/outLo), pitch NC
template<int EPI, int OUT>
__global__ void __launch_bounds__(256, 2)
gemm_tc(const uint32_t* __restrict__ Ahi, const uint32_t* __restrict__ Alo,
        const uint32_t* __restrict__ Bhi, const uint32_t* __restrict__ Blo,
        float* __restrict__ C, int K, int NC,
        const float* __restrict__ bias, const float* __restrict__ resid,
        const int* __restrict__ maskTok,
        uint32_t* __restrict__ outHi, uint32_t* __restrict__ outLo) {
    extern __shared__ uint32_t sm[];
    const int tid = threadIdx.x;
    const int lane = tid & 31, warp = tid >> 5;
    const int wm = warp & 1, wn = warp >> 1;
    const int g = lane >> 2, tq = lane & 3;
    const int NS = K >> 5;
    const size_t aBase = (size_t)blockIdx.y * NS * 2048;
    const size_t bBase = (size_t)blockIdx.x * NS * 2048;
    const uint32_t smBase = (uint32_t)__cvta_generic_to_shared(sm);

    float acc[4][4][4];
    #pragma unroll
    for (int mt = 0; mt < 4; mt++)
        #pragma unroll
        for (int nt = 0; nt < 4; nt++)
            #pragma unroll
            for (int r = 0; r < 4; r++) acc[mt][nt][r] = 0.f;

    // issue stage s into buffer buf
    auto issue = [&](int s, int buf) {
        uint32_t d = smBase + buf * 32768 + tid * 16;
        const uint32_t* a1 = Ahi + aBase + (size_t)s * 2048 + tid * 4;
        const uint32_t* a2 = Alo + aBase + (size_t)s * 2048 + tid * 4;
        const uint32_t* b1 = Bhi + bBase + (size_t)s * 2048 + tid * 4;
        const uint32_t* b2 = Blo + bBase + (size_t)s * 2048 + tid * 4;
        cp16(d,          a1); cp16(d + 4096,  a1 + 1024);
        cp16(d + 8192,   a2); cp16(d + 12288, a2 + 1024);
        cp16(d + 16384,  b1); cp16(d + 20480, b1 + 1024);
        cp16(d + 24576,  b2); cp16(d + 28672, b2 + 1024);
    };

    issue(0, 0); cp_commit();
    issue(1, 1); cp_commit();

    for (int s = 0; s < NS; s++) {
        cp_wait1();
        __syncthreads();
        int base = (s & 1) * 8192;
        #pragma unroll
        for (int kb = 0; kb < 2; kb++) {
            uint4 Ah[4], Al[4]; uint2 Bh[4], Bl[4];
            #pragma unroll
            for (int mt = 0; mt < 4; mt++) {
                int blk = base + ((wm * 4 + mt) * 2 + kb) * 128 + lane * 4;
                Ah[mt] = *(uint4*)&sm[blk];
                Al[mt] = *(uint4*)&sm[blk + 2048];
            }
            #pragma unroll
            for (int nt = 0; nt < 4; nt++) {
                int bo = base + 4096 + (kb * 16 + wn * 4 + nt) * 64 + lane * 2;
                Bh[nt] = *(uint2*)&sm[bo];
                Bl[nt] = *(uint2*)&sm[bo + 2048];
            }
            #pragma unroll
            for (int mt = 0; mt < 4; mt++)
                #pragma unroll
                for (int nt = 0; nt < 4; nt++)
                    mma_bf16(acc[mt][nt], Ah[mt], Bh[nt]);
            #pragma unroll
            for (int mt = 0; mt < 4; mt++)
                #pragma unroll
                for (int nt = 0; nt < 4; nt++)
                    mma_bf16(acc[mt][nt], Ah[mt], Bl[nt]);
            #pragma unroll
            for (int mt = 0; mt < 4; mt++)
                #pragma unroll
                for (int nt = 0; nt < 4; nt++)
                    mma_bf16(acc[mt][nt], Al[mt], Bh[nt]);
        }
        __syncthreads();
        if (s + 2 < NS) { issue(s + 2, s & 1); cp_commit(); }
    }

    const long rowBase = (long)blockIdx.y * 128;
    const int colBase = blockIdx.x * 128;

    if (OUT == 1) {
        // split-permuted output (EPI 3: gelu + bias)
        #pragma unroll
        for (int mt = 0; mt < 4; mt++) {
            float tv[4][4];
            #pragma unroll
            for (int nt = 0; nt < 4; nt++) {
                int c = colBase + wn * 32 + nt * 8 + 2 * tq;
                float b0 = bias[c], b1 = bias[c + 1];
                tv[nt][0] = gelu_tanh(acc[mt][nt][0] + b0);
                tv[nt][1] = gelu_tanh(acc[mt][nt][1] + b1);
                tv[nt][2] = gelu_tanh(acc[mt][nt][2] + b0);
                tv[nt][3] = gelu_tanh(acc[mt][nt][3] + b1);
            }
            #pragma unroll
            for (int ntp = 0; ntp < 2; ntp++) {
                uint4 hv, lv;
                split_pack(tv[2*ntp][0],   tv[2*ntp][1],   hv.x, lv.x);
                split_pack(tv[2*ntp][2],   tv[2*ntp][3],   hv.y, lv.y);
                split_pack(tv[2*ntp+1][0], tv[2*ntp+1][1], hv.z, lv.z);
                split_pack(tv[2*ntp+1][2], tv[2*ntp+1][3], hv.w, lv.w);
                size_t I = ((size_t)blockIdx.y * (NC >> 5) + blockIdx.x * 4 + wn) * 2048
                         + ((wm * 4 + mt) * 2 + ntp) * 128 + g * 16 + tq * 4;
                *(uint4*)&outHi[I] = hv;
                *(uint4*)&outLo[I] = lv;
            }
        }
        return;
    }

    #pragma unroll
    for (int mt = 0; mt < 4; mt++) {
        long r0 = rowBase + wm * 64 + mt * 16 + g;
        long r1 = r0 + 8;
        float m0 = 1.f, m1 = 1.f;
        if (EPI == 2) {
            m0 = (maskTok[r0] > 0) ? 1.f : 0.f;
            m1 = (maskTok[r1] > 0) ? 1.f : 0.f;
        }
        #pragma unroll
        for (int nt = 0; nt < 4; nt++) {
            int c = colBase + wn * 32 + nt * 8 + 2 * tq;
            float v0 = acc[mt][nt][0], v1 = acc[mt][nt][1];
            float v2 = acc[mt][nt][2], v3 = acc[mt][nt][3];
            if (EPI == 1) {
                v0 = fmaxf(v0, 0.f) + KEPS; v1 = fmaxf(v1, 0.f) + KEPS;
                v2 = fmaxf(v2, 0.f) + KEPS; v3 = fmaxf(v3, 0.f) + KEPS;
            }
            if (EPI == 2) {
                v0 = (fmaxf(v0, 0.f) + KEPS) * m0; v1 = (fmaxf(v1, 0.f) + KEPS) * m0;
                v2 = (fmaxf(v2, 0.f) + KEPS) * m1; v3 = (fmaxf(v3, 0.f) + KEPS) * m1;
            }
            if (EPI == 4) {
                float b0 = bias[c], b1 = bias[c + 1];
                v0 += b0 + resid[(size_t)r0 * NC + c];
                v1 += b1 + resid[(size_t)r0 * NC + c + 1];
                v2 += b0 + resid[(size_t)r1 * NC + c];
                v3 += b1 + resid[(size_t)r1 * NC + c + 1];
            }
            if (EPI == 5) {
                v0 += resid[(size_t)r0 * NC + c];
                v1 += resid[(size_t)r0 * NC + c + 1];
                v2 += resid[(size_t)r1 * NC + c];
                v3 += resid[(size_t)r1 * NC + c + 1];
            }
            float2 o0 = {v0, v1}, o1 = {v2, v3};
            *(float2*)&C[(size_t)r0 * NC + c] = o0;
            *(float2*)&C[(size_t)r1 * NC + c] = o1;
        }
    }
}

// ---------------- zero kv/z -----------------------------------------------
__global__ void zero_kv_kernel(float* kv, float* z) {
    int i = blockIdx.x * blockDim.x + threadIdx.x;
    if (i < Bz * Hz * Dz * Dz) kv[i] = 0.f;
    if (i < Bz * Hz * Dz) z[i] = 0.f;
}

// ---------------- kv = phik^T @ v (per b,h), z = sum phik ------------------
#define KV_SPLITS 8
__global__ void kv_kernel(const float* __restrict__ phik,
                          const float* __restrict__ v,
                          float* __restrict__ kv, float* __restrict__ z) {
    int bh = blockIdx.x;
    int split = blockIdx.y;
    int b = bh >> 3, h = bh & 7;
    const int CH = Sz / KV_SPLITS;
    int s0 = split * CH;
    __shared__ float ks[32][64];
    __shared__ float vs[32][64];
    int tid = threadIdx.x;
    int tx = tid & 15, ty = tid >> 4;

    float acc[4][4];
    #pragma unroll
    for (int i = 0; i < 4; i++)
        #pragma unroll
        for (int j = 0; j < 4; j++) acc[i][j] = 0.f;
    float zacc[4] = {0.f, 0.f, 0.f, 0.f};

    for (int c = 0; c < CH; c += 32) {
        #pragma unroll
        for (int r = 0; r < 2; r++) {
            int f4 = tid + r * 256;
            int row = f4 >> 4;
            int col = (f4 & 15) * 4;
            size_t base = ((size_t)(b * Sz + s0 + c + row)) * Ez + h * 64 + col;
            *(float4*)&ks[row][col] = *(const float4*)&phik[base];
            *(float4*)&vs[row][col] = *(const float4*)&v[base];
        }
        __syncthreads();
        #pragma unroll
        for (int s = 0; s < 32; s++) {
            float a[4], bb[4];
            #pragma unroll
            for (int i = 0; i < 4; i++) { a[i] = ks[s][ty * 4 + i]; bb[i] = vs[s][tx * 4 + i]; }
            #pragma unroll
            for (int i = 0; i < 4; i++)
                #pragma unroll
                for (int j = 0; j < 4; j++) acc[i][j] = fmaf(a[i], bb[j], acc[i][j]);
            if (tx == 0) {
                #pragma unroll
                for (int i = 0; i < 4; i++) zacc[i] += a[i];
            }
        }
        __syncthreads();
    }
    float* kvp = kv + bh * Dz * Dz;
    #pragma unroll
    for (int i = 0; i < 4; i++)
        #pragma unroll
        for (int j = 0; j < 4; j++)
            atomicAdd(&kvp[(ty * 4 + i) * 64 + tx * 4 + j], acc[i][j]);
    if (tx == 0) {
        #pragma unroll
        for (int i = 0; i < 4; i++)
            atomicAdd(&z[bh * 64 + ty * 4 + i], zacc[i]);
    }
}

// ---------------- numden: out = (phiq @ kv) / (phiq . z), split-perm out ----
__global__ void numden_split(const float* __restrict__ phiq,
                             const float* __restrict__ kv,
                             const float* __restrict__ z,
                             uint32_t* __restrict__ outHi,
                             uint32_t* __restrict__ outLo) {
    int bh = blockIdx.x;
    int chunk = blockIdx.y;       // 64 rows
    int b = bh >> 3, h = bh & 7;
    __shared__ float kvs[64][65];
    __shared__ float zs[64];
    __shared__ float pqs[4][64];
    __shared__ float nd[64][65];
    int tid = threadIdx.x;
    int tx = tid & 63, ty = tid >> 6;

    for (int idx = tid; idx < 4096; idx += 256) {
        int r = idx >> 6, c = idx & 63;
        kvs[r][c] = kv[bh * Dz * Dz + idx];
    }
    if (tid < 64) zs[tid] = z[bh * 64 + tid];
    __syncthreads();

    int s0 = chunk * 64;
    for (int it = 0; it < 16; it++) {
        int sl = it * 4 + ty;
        size_t base = ((size_t)(b * Sz + s0 + sl)) * Ez + h * 64;
        pqs[ty][tx] = phiq[base + tx];
        __syncthreads();
        float num = 0.f, den = 0.f;
        #pragma unroll
        for (int m = 0; m < 64; m++) {
            float p = pqs[ty][m];
            num = fmaf(p, kvs[m][tx], num);
            den = fmaf(p, zs[m], den);
        }
        nd[sl][tx] = num / den;
        __syncthreads();
    }

    // write phase: rows b*Sz + chunk*64 .. +63, cols h*64..h*64+63
    int g = tid & 7, halfRun = (tid >> 3) & 1, kb = (tid >> 4) & 1;
    int s2 = (tid >> 5) & 1, mtl = tid >> 6;
    long rowTile = ((long)b * Sz + chunk * 64) >> 7;
    int mtG = (chunk & 1) * 4 + mtl;
    int stage = h * 2 + s2;
    uint32_t hi[8], lo[8];
    #pragma unroll
    for (int o = 0; o < 8; o++) {
        int tqv = halfRun * 2 + (o >> 2);
        int kbit = (o >> 1) & 1, rbit = o & 1;
        int rl = mtl * 16 + g + 8 * rbit;
        int cl = s2 * 32 + kb * 16 + 2 * tqv + 8 * kbit;
        split_pack(nd[rl][cl], nd[rl][cl + 1], hi[o], lo[o]);
    }
    size_t I = ((size_t)(rowTile * 16 + stage)) * 2048
             + (mtG * 2 + kb) * 128 + g * 16 + halfRun * 8;
    *(uint4*)&outHi[I]     = *(uint4*)&hi[0];
    *(uint4*)&outHi[I + 4] = *(uint4*)&hi[4];
    *(uint4*)&outLo[I]     = *(uint4*)&lo[0];
    *(uint4*)&outLo[I + 4] = *(uint4*)&lo[4];
}

// ---------------- host side ------------------------------------------------
#define SMEM_BYTES 65536

extern "C" void kernel_launch(void* const* d_in, const int* in_sizes, int n_in,
                              void* d_out, int out_size) {
    const int*   inputs    = (const int*)  d_in[0];
    const float* embed     = (const float*)d_in[1];
    const float* ln1_scale = (const float*)d_in[2];
    const float* ln1_bias  = (const float*)d_in[3];
    const float* wq        = (const float*)d_in[4];
    const float* wk        = (const float*)d_in[5];
    const float* wv        = (const float*)d_in[6];
    const float* wo        = (const float*)d_in[7];
    const float* ln2_scale = (const float*)d_in[8];
    const float* ln2_bias  = (const float*)d_in[9];
    const float* w1        = (const float*)d_in[10];
    const float* b1        = (const float*)d_in[11];
    const float* w2        = (const float*)d_in[12];
    const float* b2        = (const float*)d_in[13];
    const float* lnf_scale = (const float*)d_in[14];
    const float* lnf_bias  = (const float*)d_in[15];
    float* out = (float*)d_out;

    static float *px = nullptr, *pq, *pk, *pv, *pkv, *pz;
    static uint32_t *hAhi, *hAlo, *ndhi, *ndlo, *pthi, *ptlo, *whi, *wlo;
    if (!px) {
        cudaGetSymbolAddress((void**)&px,   g_x);
        cudaGetSymbolAddress((void**)&pq,   g_phiq);
        cudaGetSymbolAddress((void**)&pk,   g_phik);
        cudaGetSymbolAddress((void**)&pv,   g_v);
        cudaGetSymbolAddress((void**)&pkv,  g_kv);
        cudaGetSymbolAddress((void**)&pz,   g_z);
        cudaGetSymbolAddress((void**)&hAhi, g_hAhi);
        cudaGetSymbolAddress((void**)&hAlo, g_hAlo);
        cudaGetSymbolAddress((void**)&ndhi, g_ndhi);
        cudaGetSymbolAddress((void**)&ndlo, g_ndlo);
        cudaGetSymbolAddress((void**)&pthi, g_pthi);
        cudaGetSymbolAddress((void**)&ptlo, g_ptlo);
        cudaGetSymbolAddress((void**)&whi,  g_whi);
        cudaGetSymbolAddress((void**)&wlo,  g_wlo);
        cudaFuncSetAttribute(gemm_tc<0,0>, cudaFuncAttributeMaxDynamicSharedMemorySize, SMEM_BYTES);
        cudaFuncSetAttribute(gemm_tc<1,0>, cudaFuncAttributeMaxDynamicSharedMemorySize, SMEM_BYTES);
        cudaFuncSetAttribute(gemm_tc<2,0>, cudaFuncAttributeMaxDynamicSharedMemorySize, SMEM_BYTES);
        cudaFuncSetAttribute(gemm_tc<3,1>, cudaFuncAttributeMaxDynamicSharedMemorySize, SMEM_BYTES);
        cudaFuncSetAttribute(gemm_tc<4,0>, cudaFuncAttributeMaxDynamicSharedMemorySize, SMEM_BYTES);
        cudaFuncSetAttribute(gemm_tc<5,0>, cudaFuncAttributeMaxDynamicSharedMemorySize, SMEM_BYTES);
    }

    // 1. weight split pre-pass (all layers)
    split_w<<<dim3(Ez/256, Ez/16, Lz), 256>>>(wq, whi + OQ,  wlo + OQ,  Ez, Ez, (size_t)Ez*Ez, 131072);
    split_w<<<dim3(Ez/256, Ez/16, Lz), 256>>>(wk, whi + OK_, wlo + OK_, Ez, Ez, (size_t)Ez*Ez, 131072);
    split_w<<<dim3(Ez/256, Ez/16, Lz), 256>>>(wv, whi + OV,  wlo + OV,  Ez, Ez, (size_t)Ez*Ez, 131072);
    split_w<<<dim3(Ez/256, Ez/16, Lz), 256>>>(wo, whi + OO,  wlo + OO,  Ez, Ez, (size_t)Ez*Ez, 131072);
    split_w<<<dim3(Mz/256, Ez/16, Lz), 256>>>(w1, whi + O1,  wlo + O1,  Ez, Mz, (size_t)Ez*Mz, 524288);
    split_w<<<dim3(Ez/256, Mz/16, Lz), 256>>>(w2, whi + O2,  wlo + O2,  Mz, Ez, (size_t)Mz*Ez, 524288);

    // 2. embedding + positional encoding
    embed_pe_kernel<<<(Nrows * Ez + 255) / 256, 256>>>(inputs, embed, px);

    dim3 gE(Ez / 128, Nrows / 128);
    dim3 gM(Mz / 128, Nrows / 128);
    dim3 gKV(Bz * Hz, KV_SPLITS);
    dim3 gND(Bz * Hz, Sz / 64);

    for (int l = 0; l < Lz; l++) {
        const uint32_t* wqh = whi + OQ  + (size_t)l * 131072;
        const uint32_t* wql = wlo + OQ  + (size_t)l * 131072;
        const uint32_t* wkh = whi + OK_ + (size_t)l * 131072;
        const uint32_t* wkl = wlo + OK_ + (size_t)l * 131072;
        const uint32_t* wvh = whi + OV  + (size_t)l * 131072;
        const uint32_t* wvl = wlo + OV  + (size_t)l * 131072;
        const uint32_t* woh = whi + OO  + (size_t)l * 131072;
        const uint32_t* wol = wlo + OO  + (size_t)l * 131072;
        const uint32_t* w1h = whi + O1  + (size_t)l * 524288;
        const uint32_t* w1l = wlo + O1  + (size_t)l * 524288;
        const uint32_t* w2h = whi + O2  + (size_t)l * 524288;
        const uint32_t* w2l = wlo + O2  + (size_t)l * 524288;

        layernorm_split<<<Nrows / 16, 256>>>(px, hAhi, hAlo,
                                             ln1_scale + l * Ez, ln1_bias + l * Ez);
        gemm_tc<1,0><<<gE, 256, SMEM_BYTES>>>(hAhi, hAlo, wqh, wql, pq, Ez, Ez,
                                              nullptr, nullptr, nullptr, nullptr, nullptr);
        gemm_tc<2,0><<<gE, 256, SMEM_BYTES>>>(hAhi, hAlo, wkh, wkl, pk, Ez, Ez,
                                              nullptr, nullptr, inputs, nullptr, nullptr);
        gemm_tc<0,0><<<gE, 256, SMEM_BYTES>>>(hAhi, hAlo, wvh, wvl, pv, Ez, Ez,
                                              nullptr, nullptr, nullptr, nullptr, nullptr);
        zero_kv_kernel<<<(Bz * Hz * Dz * Dz + 255) / 256, 256>>>(pkv, pz);
        kv_kernel<<<gKV, 256>>>(pk, pv, pkv, pz);
        numden_split<<<gND, 256>>>(pq, pkv, pz, ndhi, ndlo);
        gemm_tc<5,0><<<gE, 256, SMEM_BYTES>>>(ndhi, ndlo, woh, wol, px, Ez, Ez,
                                              nullptr, px, nullptr, nullptr, nullptr);
        layernorm_split<<<Nrows / 16, 256>>>(px, hAhi, hAlo,
                                             ln2_scale + l * Ez, ln2_bias + l * Ez);
        gemm_tc<3,1><<<gM, 256, SMEM_BYTES>>>(hAhi, hAlo, w1h, w1l, nullptr, Ez, Mz,
                                              b1 + (size_t)l * Mz, nullptr, nullptr, pthi, ptlo);
        gemm_tc<4,0><<<gE, 256, SMEM_BYTES>>>(pthi, ptlo, w2h, w2l, px, Mz, Ez,
                                              b2 + (size_t)l * Ez, px, nullptr, nullptr, nullptr);
    }

    layernorm_kernel<<<Nrows, 256>>>(px, out, lnf_scale, lnf_bias);
}

// round 5
// speedup vs baseline: 3.0568x; 1.0007x over previous
#include <cuda_runtime.h>
#include <cuda_bf16.h>
#include <math.h>
#include <stdint.h>

// Problem constants
#define Bz 4
#define Sz 4096
#define Ez 512
#define Hz 8
#define Dz 64
#define Mz 2048
#define Lz 6
#define Nrows (Bz*Sz)          // 16384
#define LN_EPS 1e-6f
#define KEPS 1e-3f

// ---------------- device scratch ----------------
__device__ float g_x[Nrows*Ez];                 // residual stream
__device__ float g_phiq[Nrows*Ez];
__device__ float g_phik[Nrows*Ez];
__device__ float g_v[Nrows*Ez];
__device__ float g_kv[Bz*Hz*Dz*Dz];
__device__ float g_z[Bz*Hz*Dz];
// split-permuted activation buffers (uint32 = packed bf16x2)
__device__ __align__(16) uint32_t g_hAhi[Nrows*256];
__device__ __align__(16) uint32_t g_hAlo[Nrows*256];
__device__ __align__(16) uint32_t g_ndhi[Nrows*256];
__device__ __align__(16) uint32_t g_ndlo[Nrows*256];
__device__ __align__(16) uint32_t g_pthi[Nrows*1024];
__device__ __align__(16) uint32_t g_ptlo[Nrows*1024];
// split-permuted weights: [qkv,o: 6*131072 each][w1,w2: 6*524288 each]
#define OQ  0
#define OK_ 786432
#define OV  1572864
#define OO  2359296
#define O1  3145728
#define O2  6291456
#define WTOT 9437184
__device__ __align__(16) uint32_t g_whi[WTOT];
__device__ __align__(16) uint32_t g_wlo[WTOT];

// ---------------- helpers ----------------
__device__ __forceinline__ void split_pack(float x0, float x1,
                                           uint32_t& hi, uint32_t& lo) {
    __nv_bfloat162 h = __floats2bfloat162_rn(x0, x1);
    float r0 = x0 - __bfloat162float(h.x);
    float r1 = x1 - __bfloat162float(h.y);
    __nv_bfloat162 l = __floats2bfloat162_rn(r0, r1);
    hi = *reinterpret_cast<uint32_t*>(&h);
    lo = *reinterpret_cast<uint32_t*>(&l);
}

__device__ __forceinline__ void mma_bf16(float* c, uint4 a, uint2 b) {
    asm volatile(
        "mma.sync.aligned.m16n8k16.row.col.f32.bf16.bf16.f32 "
        "{%0,%1,%2,%3}, {%4,%5,%6,%7}, {%8,%9}, {%0,%1,%2,%3};"
        : "+f"(c[0]), "+f"(c[1]), "+f"(c[2]), "+f"(c[3])
        : "r"(a.x), "r"(a.y), "r"(a.z), "r"(a.w), "r"(b.x), "r"(b.y));
}

__device__ __forceinline__ float warp_sum(float v) {
    #pragma unroll
    for (int o = 16; o; o >>= 1) v += __shfl_xor_sync(0xffffffffu, v, o);
    return v;
}

__device__ __forceinline__ float gelu_tanh(float x) {
    float x3 = x * x * x;
    return 0.5f * x * (1.f + tanhf(0.7978845608028654f * (x + 0.044715f * x3)));
}

__device__ __forceinline__ void cp16(uint32_t dst, const void* src) {
    asm volatile("cp.async.cg.shared.global [%0], [%1], 16;\n" :: "r"(dst), "l"(src));
}
__device__ __forceinline__ void cp_commit() {
    asm volatile("cp.async.commit_group;\n");
}
__device__ __forceinline__ void cp_wait1() {
    asm volatile("cp.async.wait_group 1;\n");
}

// ---------------- weight split pre-pass ----------------
// W [K][NC] fp32 -> perm layout: [colTile cb][stage][2048]:
//   uint32 at (kbS*16+nb)*64 + (g*4+tq)*2 + h = pack(W[k][c], W[k+1][c])
//   where c = cb*128+nb*8+g, k = stage*32 + kbS*16 + 2tq + 8h
__global__ void split_w(const float* __restrict__ W,
                        uint32_t* __restrict__ hi, uint32_t* __restrict__ lo,
                        int K, int NC, size_t wStrideL, size_t oStrideL) {
    int l = blockIdx.z;
    const float* Wl = W + (size_t)l * wStrideL;
    uint32_t* hiL = hi + (size_t)l * oStrideL;
    uint32_t* loL = lo + (size_t)l * oStrideL;
    int c = blockIdx.x * 256 + threadIdx.x;
    int kb = blockIdx.y;                 // 0..K/16-1
    int cb = c >> 7, nb = (c >> 3) & 15, g = c & 7;
    int stage = kb >> 1, kbS = kb & 1;
    uint32_t h8[8], l8[8];
    #pragma unroll
    for (int o = 0; o < 8; o++) {
        int tq = o >> 1, hb = o & 1;
        int k = kb * 16 + 2 * tq + 8 * hb;
        float x0 = Wl[(size_t)k * NC + c];
        float x1 = Wl[(size_t)(k + 1) * NC + c];
        split_pack(x0, x1, h8[o], l8[o]);
    }
    size_t I = ((size_t)(cb * (K >> 5) + stage)) * 2048 + (kbS * 16 + nb) * 64 + g * 8;
    *(uint4*)&hiL[I]     = *(uint4*)&h8[0];
    *(uint4*)&hiL[I + 4] = *(uint4*)&h8[4];
    *(uint4*)&loL[I]     = *(uint4*)&l8[0];
    *(uint4*)&loL[I + 4] = *(uint4*)&l8[4];
}

// ---------------- embedding + sinusoidal PE ----------------
__global__ void embed_pe_kernel(const int* __restrict__ inp,
                                const float* __restrict__ emb,
                                float* __restrict__ x) {
    int idx = blockIdx.x * blockDim.x + threadIdx.x;
    if (idx >= Nrows * Ez) return;
    int e = idx & (Ez - 1);
    int n = idx >> 9;
    int s = n & (Sz - 1);
    int tok = inp[n];
    int j = (e >> 1) * 2;
    const float c = -9.210340371976184f / (float)Ez;
    float ang = (float)s * expf((float)j * c);
    float pe = (e & 1) ? cosf(ang) : sinf(ang);
    x[idx] = emb[(size_t)tok * Ez + e] + pe;
}

// ---------------- layernorm -> fp32 (final only) ----------------
__device__ __forceinline__ float block_sum(float val, float* red) {
    __syncthreads();
    int t = threadIdx.x;
    #pragma unroll
    for (int o = 16; o; o >>= 1) val += __shfl_down_sync(0xffffffffu, val, o);
    if ((t & 31) == 0) red[t >> 5] = val;
    __syncthreads();
    if (t < 32) {
        float r = (t < 8) ? red[t] : 0.f;
        #pragma unroll
        for (int o = 4; o; o >>= 1) r += __shfl_down_sync(0xffffffffu, r, o);
        if (t == 0) red[0] = r;
    }
    __syncthreads();
    return red[0];
}

__global__ void layernorm_kernel(const float* __restrict__ in,
                                 float* __restrict__ out,
                                 const float* __restrict__ scale,
                                 const float* __restrict__ bias) {
    __shared__ float red[32];
    int n = blockIdx.x;
    int t = threadIdx.x;
    const float* row = in + (size_t)n * Ez;
    float2 v = *(const float2*)&row[t * 2];
    float mu = block_sum(v.x + v.y, red) * (1.f / Ez);
    float dx = v.x - mu, dy = v.y - mu;
    float var = block_sum(dx * dx + dy * dy, red) * (1.f / Ez);
    float rs = rsqrtf(var + LN_EPS);
    float2 o;
    o.x = dx * rs * scale[t * 2 + 0] + bias[t * 2 + 0];
    o.y = dy * rs * scale[t * 2 + 1] + bias[t * 2 + 1];
    *(float2*)&out[(size_t)n * Ez + t * 2] = o;
}

// ---------------- layernorm -> split-permuted output ----------------
// block = 256 threads, 16 rows. pitch E=512 -> 16 stages.
__global__ void layernorm_split(const float* __restrict__ in,
                                uint32_t* __restrict__ outHi,
                                uint32_t* __restrict__ outLo,
                                const float* __restrict__ scale,
                                const float* __restrict__ bias) {
    __shared__ float nrm[16][516];
    int tid = threadIdx.x;
    int warp = tid >> 5, lane = tid & 31;
    long n0 = (long)blockIdx.x * 16;

    #pragma unroll
    for (int rr = 0; rr < 2; rr++) {
        int r = warp * 2 + rr;
        const float* row = in + (n0 + r) * Ez;
        float4 v[4];
        float s = 0.f;
        #pragma unroll
        for (int q = 0; q < 4; q++) {
            v[q] = *(const float4*)&row[lane * 4 + q * 128];
            s += v[q].x + v[q].y + v[q].z + v[q].w;
        }
        float mu = warp_sum(s) * (1.f / Ez);
        float vr = 0.f;
        #pragma unroll
        for (int q = 0; q < 4; q++) {
            float a = v[q].x - mu, b = v[q].y - mu, c = v[q].z - mu, d = v[q].w - mu;
            vr += a * a + b * b + c * c + d * d;
        }
        float rs = rsqrtf(warp_sum(vr) * (1.f / Ez) + LN_EPS);
        #pragma unroll
        for (int q = 0; q < 4; q++) {
            int c = lane * 4 + q * 128;
            float4 sc = *(const float4*)&scale[c];
            float4 bi = *(const float4*)&bias[c];
            float4 o;
            o.x = (v[q].x - mu) * rs * sc.x + bi.x;
            o.y = (v[q].y - mu) * rs * sc.y + bi.y;
            o.z = (v[q].z - mu) * rs * sc.z + bi.z;
            o.w = (v[q].w - mu) * rs * sc.w + bi.w;
            *(float4*)&nrm[r][c] = o;
        }
    }
    __syncthreads();

    // write phase: thread (stage, kb, g) writes 16 contiguous uint32
    int g = tid & 7, kb = (tid >> 3) & 1, stage = tid >> 4;
    uint32_t hi[16], lo[16];
    #pragma unroll
    for (int o = 0; o < 16; o++) {
        int tq = o >> 2, kbit = (o >> 1) & 1, rbit = o & 1;
        int c = stage * 32 + kb * 16 + 2 * tq + 8 * kbit;
        int rl = g + 8 * rbit;
        split_pack(nrm[rl][c], nrm[rl][c + 1], hi[o], lo[o]);
    }
    size_t I = ((size_t)((blockIdx.x >> 3) * 16 + stage)) * 2048
             + ((blockIdx.x & 7) * 2 + kb) * 128 + g * 16;
    *(uint4*)&outHi[I]      = *(uint4*)&hi[0];
    *(uint4*)&outHi[I + 4]  = *(uint4*)&hi[4];
    *(uint4*)&outHi[I + 8]  = *(uint4*)&hi[8];
    *(uint4*)&outHi[I + 12] = *(uint4*)&hi[12];
    *(uint4*)&outLo[I]      = *(uint4*)&lo[0];
    *(uint4*)&outLo[I + 4]  = *(uint4*)&lo[4];
    *(uint4*)&outLo[I + 8]  = *(uint4*)&lo[8];
    *(uint4*)&outLo[I + 12] = *(uint4*)&lo[12];
}

// ---------------- tensor-core GEMM (pre-split, cp.async pipeline) ----------
// EPI: 0 plain, 1 relu+eps, 2 (relu+eps)*mask, 3 gelu(x+bias),
//      4 x+bias+resid, 5 x+resid
// OUT: 0 = fp32 C, 1 = split-permuted (outHi/outLo), pitch NC
template<int EPI, int OUT>
__global__ void __launch_bounds__(256, 2)
gemm_tc(const uint32_t* __restrict__ Ahi, const uint32_t* __restrict__ Alo,
        const uint32_t* __restrict__ Bhi, const uint32_t* __restrict__ Blo,
        float* __restrict__ C, int K, int NC,
        const float* __restrict__ bias, const float* __restrict__ resid,
        const int* __restrict__ maskTok,
        uint32_t* __restrict__ outHi, uint32_t* __restrict__ outLo) {
    extern __shared__ uint32_t sm[];
    const int tid = threadIdx.x;
    const int lane = tid & 31, warp = tid >> 5;
    const int wm = warp & 1, wn = warp >> 1;
    const int g = lane >> 2, tq = lane & 3;
    const int NS = K >> 5;
    const size_t aBase = (size_t)blockIdx.y * NS * 2048;
    const size_t bBase = (size_t)blockIdx.x * NS * 2048;
    const uint32_t smBase = (uint32_t)__cvta_generic_to_shared(sm);

    float acc[4][4][4];
    #pragma unroll
    for (int mt = 0; mt < 4; mt++)
        #pragma unroll
        for (int nt = 0; nt < 4; nt++)
            #pragma unroll
            for (int r = 0; r < 4; r++) acc[mt][nt][r] = 0.f;

    // issue stage s into buffer buf
    auto issue = [&](int s, int buf) {
        uint32_t d = smBase + buf * 32768 + tid * 16;
        const uint32_t* a1 = Ahi + aBase + (size_t)s * 2048 + tid * 4;
        const uint32_t* a2 = Alo + aBase + (size_t)s * 2048 + tid * 4;
        const uint32_t* b1 = Bhi + bBase + (size_t)s * 2048 + tid * 4;
        const uint32_t* b2 = Blo + bBase + (size_t)s * 2048 + tid * 4;
        cp16(d,          a1); cp16(d + 4096,  a1 + 1024);
        cp16(d + 8192,   a2); cp16(d + 12288, a2 + 1024);
        cp16(d + 16384,  b1); cp16(d + 20480, b1 + 1024);
        cp16(d + 24576,  b2); cp16(d + 28672, b2 + 1024);
    };

    issue(0, 0); cp_commit();
    issue(1, 1); cp_commit();

    for (int s = 0; s < NS; s++) {
        cp_wait1();
        __syncthreads();
        int base = (s & 1) * 8192;
        #pragma unroll
        for (int kb = 0; kb < 2; kb++) {
            uint4 Ah[4], Al[4]; uint2 Bh[4], Bl[4];
            #pragma unroll
            for (int mt = 0; mt < 4; mt++) {
                int blk = base + ((wm * 4 + mt) * 2 + kb) * 128 + lane * 4;
                Ah[mt] = *(uint4*)&sm[blk];
                Al[mt] = *(uint4*)&sm[blk + 2048];
            }
            #pragma unroll
            for (int nt = 0; nt < 4; nt++) {
                int bo = base + 4096 + (kb * 16 + wn * 4 + nt) * 64 + lane * 2;
                Bh[nt] = *(uint2*)&sm[bo];
                Bl[nt] = *(uint2*)&sm[bo + 2048];
            }
            #pragma unroll
            for (int mt = 0; mt < 4; mt++)
                #pragma unroll
                for (int nt = 0; nt < 4; nt++)
                    mma_bf16(acc[mt][nt], Ah[mt], Bh[nt]);
            #pragma unroll
            for (int mt = 0; mt < 4; mt++)
                #pragma unroll
                for (int nt = 0; nt < 4; nt++)
                    mma_bf16(acc[mt][nt], Ah[mt], Bl[nt]);
            #pragma unroll
            for (int mt = 0; mt < 4; mt++)
                #pragma unroll
                for (int nt = 0; nt < 4; nt++)
                    mma_bf16(acc[mt][nt], Al[mt], Bh[nt]);
        }
        __syncthreads();
        if (s + 2 < NS) { issue(s + 2, s & 1); cp_commit(); }
    }

    const long rowBase = (long)blockIdx.y * 128;
    const int colBase = blockIdx.x * 128;

    if (OUT == 1) {
        // split-permuted output (EPI 3: gelu + bias)
        #pragma unroll
        for (int mt = 0; mt < 4; mt++) {
            float tv[4][4];
            #pragma unroll
            for (int nt = 0; nt < 4; nt++) {
                int c = colBase + wn * 32 + nt * 8 + 2 * tq;
                float b0 = bias[c], b1 = bias[c + 1];
                tv[nt][0] = gelu_tanh(acc[mt][nt][0] + b0);
                tv[nt][1] = gelu_tanh(acc[mt][nt][1] + b1);
                tv[nt][2] = gelu_tanh(acc[mt][nt][2] + b0);
                tv[nt][3] = gelu_tanh(acc[mt][nt][3] + b1);
            }
            #pragma unroll
            for (int ntp = 0; ntp < 2; ntp++) {
                uint4 hv, lv;
                split_pack(tv[2*ntp][0],   tv[2*ntp][1],   hv.x, lv.x);
                split_pack(tv[2*ntp][2],   tv[2*ntp][3],   hv.y, lv.y);
                split_pack(tv[2*ntp+1][0], tv[2*ntp+1][1], hv.z, lv.z);
                split_pack(tv[2*ntp+1][2], tv[2*ntp+1][3], hv.w, lv.w);
                size_t I = ((size_t)blockIdx.y * (NC >> 5) + blockIdx.x * 4 + wn) * 2048
                         + ((wm * 4 + mt) * 2 + ntp) * 128 + g * 16 + tq * 4;
                *(uint4*)&outHi[I] = hv;
                *(uint4*)&outLo[I] = lv;
            }
        }
        return;
    }

    #pragma unroll
    for (int mt = 0; mt < 4; mt++) {
        long r0 = rowBase + wm * 64 + mt * 16 + g;
        long r1 = r0 + 8;
        float m0 = 1.f, m1 = 1.f;
        if (EPI == 2) {
            m0 = (maskTok[r0] > 0) ? 1.f : 0.f;
            m1 = (maskTok[r1] > 0) ? 1.f : 0.f;
        }
        #pragma unroll
        for (int nt = 0; nt < 4; nt++) {
            int c = colBase + wn * 32 + nt * 8 + 2 * tq;
            float v0 = acc[mt][nt][0], v1 = acc[mt][nt][1];
            float v2 = acc[mt][nt][2], v3 = acc[mt][nt][3];
            if (EPI == 1) {
                v0 = fmaxf(v0, 0.f) + KEPS; v1 = fmaxf(v1, 0.f) + KEPS;
                v2 = fmaxf(v2, 0.f) + KEPS; v3 = fmaxf(v3, 0.f) + KEPS;
            }
            if (EPI == 2) {
                v0 = (fmaxf(v0, 0.f) + KEPS) * m0; v1 = (fmaxf(v1, 0.f) + KEPS) * m0;
                v2 = (fmaxf(v2, 0.f) + KEPS) * m1; v3 = (fmaxf(v3, 0.f) + KEPS) * m1;
            }
            if (EPI == 4) {
                float b0 = bias[c], b1 = bias[c + 1];
                v0 += b0 + resid[(size_t)r0 * NC + c];
                v1 += b1 + resid[(size_t)r0 * NC + c + 1];
                v2 += b0 + resid[(size_t)r1 * NC + c];
                v3 += b1 + resid[(size_t)r1 * NC + c + 1];
            }
            if (EPI == 5) {
                v0 += resid[(size_t)r0 * NC + c];
                v1 += resid[(size_t)r0 * NC + c + 1];
                v2 += resid[(size_t)r1 * NC + c];
                v3 += resid[(size_t)r1 * NC + c + 1];
            }
            float2 o0 = {v0, v1}, o1 = {v2, v3};
            *(float2*)&C[(size_t)r0 * NC + c] = o0;
            *(float2*)&C[(size_t)r1 * NC + c] = o1;
        }
    }
}

// ---------------- zero kv/z -----------------------------------------------
__global__ void zero_kv_kernel(float* kv, float* z) {
    int i = blockIdx.x * blockDim.x + threadIdx.x;
    if (i < Bz * Hz * Dz * Dz) kv[i] = 0.f;
    if (i < Bz * Hz * Dz) z[i] = 0.f;
}

// ---------------- kv = phik^T @ v (per b,h), z = sum phik ------------------
#define KV_SPLITS 8
__global__ void kv_kernel(const float* __restrict__ phik,
                          const float* __restrict__ v,
                          float* __restrict__ kv, float* __restrict__ z) {
    int bh = blockIdx.x;
    int split = blockIdx.y;
    int b = bh >> 3, h = bh & 7;
    const int CH = Sz / KV_SPLITS;
    int s0 = split * CH;
    __shared__ float ks[32][64];
    __shared__ float vs[32][64];
    int tid = threadIdx.x;
    int tx = tid & 15, ty = tid >> 4;

    float acc[4][4];
    #pragma unroll
    for (int i = 0; i < 4; i++)
        #pragma unroll
        for (int j = 0; j < 4; j++) acc[i][j] = 0.f;
    float zacc[4] = {0.f, 0.f, 0.f, 0.f};

    for (int c = 0; c < CH; c += 32) {
        #pragma unroll
        for (int r = 0; r < 2; r++) {
            int f4 = tid + r * 256;
            int row = f4 >> 4;
            int col = (f4 & 15) * 4;
            size_t base = ((size_t)(b * Sz + s0 + c + row)) * Ez + h * 64 + col;
            *(float4*)&ks[row][col] = *(const float4*)&phik[base];
            *(float4*)&vs[row][col] = *(const float4*)&v[base];
        }
        __syncthreads();
        #pragma unroll
        for (int s = 0; s < 32; s++) {
            float a[4], bb[4];
            #pragma unroll
            for (int i = 0; i < 4; i++) { a[i] = ks[s][ty * 4 + i]; bb[i] = vs[s][tx * 4 + i]; }
            #pragma unroll
            for (int i = 0; i < 4; i++)
                #pragma unroll
                for (int j = 0; j < 4; j++) acc[i][j] = fmaf(a[i], bb[j], acc[i][j]);
            if (tx == 0) {
                #pragma unroll
                for (int i = 0; i < 4; i++) zacc[i] += a[i];
            }
        }
        __syncthreads();
    }
    float* kvp = kv + bh * Dz * Dz;
    #pragma unroll
    for (int i = 0; i < 4; i++)
        #pragma unroll
        for (int j = 0; j < 4; j++)
            atomicAdd(&kvp[(ty * 4 + i) * 64 + tx * 4 + j], acc[i][j]);
    if (tx == 0) {
        #pragma unroll
        for (int i = 0; i < 4; i++)
            atomicAdd(&z[bh * 64 + ty * 4 + i], zacc[i]);
    }
}

// ---------------- numden: out = (phiq @ kv) / (phiq . z), split-perm out ----
__global__ void numden_split(const float* __restrict__ phiq,
                             const float* __restrict__ kv,
                             const float* __restrict__ z,
                             uint32_t* __restrict__ outHi,
                             uint32_t* __restrict__ outLo) {
    int bh = blockIdx.x;
    int chunk = blockIdx.y;       // 64 rows
    int b = bh >> 3, h = bh & 7;
    __shared__ float kvs[64][65];
    __shared__ float zs[64];
    __shared__ float pqs[4][64];
    __shared__ float nd[64][65];
    int tid = threadIdx.x;
    int tx = tid & 63, ty = tid >> 6;

    for (int idx = tid; idx < 4096; idx += 256) {
        int r = idx >> 6, c = idx & 63;
        kvs[r][c] = kv[bh * Dz * Dz + idx];
    }
    if (tid < 64) zs[tid] = z[bh * 64 + tid];
    __syncthreads();

    int s0 = chunk * 64;
    for (int it = 0; it < 16; it++) {
        int sl = it * 4 + ty;
        size_t base = ((size_t)(b * Sz + s0 + sl)) * Ez + h * 64;
        pqs[ty][tx] = phiq[base + tx];
        __syncthreads();
        float num = 0.f, den = 0.f;
        #pragma unroll
        for (int m = 0; m < 64; m++) {
            float p = pqs[ty][m];
            num = fmaf(p, kvs[m][tx], num);
            den = fmaf(p, zs[m], den);
        }
        nd[sl][tx] = num / den;
        __syncthreads();
    }

    // write phase: rows b*Sz + chunk*64 .. +63, cols h*64..h*64+63
    int g = tid & 7, halfRun = (tid >> 3) & 1, kb = (tid >> 4) & 1;
    int s2 = (tid >> 5) & 1, mtl = tid >> 6;
    long rowTile = ((long)b * Sz + chunk * 64) >> 7;
    int mtG = (chunk & 1) * 4 + mtl;
    int stage = h * 2 + s2;
    uint32_t hi[8], lo[8];
    #pragma unroll
    for (int o = 0; o < 8; o++) {
        int tqv = halfRun * 2 + (o >> 2);
        int kbit = (o >> 1) & 1, rbit = o & 1;
        int rl = mtl * 16 + g + 8 * rbit;
        int cl = s2 * 32 + kb * 16 + 2 * tqv + 8 * kbit;
        split_pack(nd[rl][cl], nd[rl][cl + 1], hi[o], lo[o]);
    }
    size_t I = ((size_t)(rowTile * 16 + stage)) * 2048
             + (mtG * 2 + kb) * 128 + g * 16 + halfRun * 8;
    *(uint4*)&outHi[I]     = *(uint4*)&hi[0];
    *(uint4*)&outHi[I + 4] = *(uint4*)&hi[4];
    *(uint4*)&outLo[I]     = *(uint4*)&lo[0];
    *(uint4*)&outLo[I + 4] = *(uint4*)&lo[4];
}

// ---------------- host side ------------------------------------------------
#define SMEM_BYTES 65536

extern "C" void kernel_launch(void* const* d_in, const int* in_sizes, int n_in,
                              void* d_out, int out_size) {
    const int*   inputs    = (const int*)  d_in[0];
    const float* embed     = (const float*)d_in[1];
    const float* ln1_scale = (const float*)d_in[2];
    const float* ln1_bias  = (const float*)d_in[3];
    const float* wq        = (const float*)d_in[4];
    const float* wk        = (const float*)d_in[5];
    const float* wv        = (const float*)d_in[6];
    const float* wo        = (const float*)d_in[7];
    const float* ln2_scale = (const float*)d_in[8];
    const float* ln2_bias  = (const float*)d_in[9];
    const float* w1        = (const float*)d_in[10];
    const float* b1        = (const float*)d_in[11];
    const float* w2        = (const float*)d_in[12];
    const float* b2        = (const float*)d_in[13];
    const float* lnf_scale = (const float*)d_in[14];
    const float* lnf_bias  = (const float*)d_in[15];
    float* out = (float*)d_out;

    static float *px = nullptr, *pq, *pk, *pv, *pkv, *pz;
    static uint32_t *hAhi, *hAlo, *ndhi, *ndlo, *pthi, *ptlo, *whi, *wlo;
    if (!px) {
        cudaGetSymbolAddress((void**)&px,   g_x);
        cudaGetSymbolAddress((void**)&pq,   g_phiq);
        cudaGetSymbolAddress((void**)&pk,   g_phik);
        cudaGetSymbolAddress((void**)&pv,   g_v);
        cudaGetSymbolAddress((void**)&pkv,  g_kv);
        cudaGetSymbolAddress((void**)&pz,   g_z);
        cudaGetSymbolAddress((void**)&hAhi, g_hAhi);
        cudaGetSymbolAddress((void**)&hAlo, g_hAlo);
        cudaGetSymbolAddress((void**)&ndhi, g_ndhi);
        cudaGetSymbolAddress((void**)&ndlo, g_ndlo);
        cudaGetSymbolAddress((void**)&pthi, g_pthi);
        cudaGetSymbolAddress((void**)&ptlo, g_ptlo);
        cudaGetSymbolAddress((void**)&whi,  g_whi);
        cudaGetSymbolAddress((void**)&wlo,  g_wlo);
        cudaFuncSetAttribute(gemm_tc<0,0>, cudaFuncAttributeMaxDynamicSharedMemorySize, SMEM_BYTES);
        cudaFuncSetAttribute(gemm_tc<1,0>, cudaFuncAttributeMaxDynamicSharedMemorySize, SMEM_BYTES);
        cudaFuncSetAttribute(gemm_tc<2,0>, cudaFuncAttributeMaxDynamicSharedMemorySize, SMEM_BYTES);
        cudaFuncSetAttribute(gemm_tc<3,1>, cudaFuncAttributeMaxDynamicSharedMemorySize, SMEM_BYTES);
        cudaFuncSetAttribute(gemm_tc<4,0>, cudaFuncAttributeMaxDynamicSharedMemorySize, SMEM_BYTES);
        cudaFuncSetAttribute(gemm_tc<5,0>, cudaFuncAttributeMaxDynamicSharedMemorySize, SMEM_BYTES);
    }

    // 1. weight split pre-pass (all layers)
    split_w<<<dim3(Ez/256, Ez/16, Lz), 256>>>(wq, whi + OQ,  wlo + OQ,  Ez, Ez, (size_t)Ez*Ez, 131072);
    split_w<<<dim3(Ez/256, Ez/16, Lz), 256>>>(wk, whi + OK_, wlo + OK_, Ez, Ez, (size_t)Ez*Ez, 131072);
    split_w<<<dim3(Ez/256, Ez/16, Lz), 256>>>(wv, whi + OV,  wlo + OV,  Ez, Ez, (size_t)Ez*Ez, 131072);
    split_w<<<dim3(Ez/256, Ez/16, Lz), 256>>>(wo, whi + OO,  wlo + OO,  Ez, Ez, (size_t)Ez*Ez, 131072);
    split_w<<<dim3(Mz/256, Ez/16, Lz), 256>>>(w1, whi + O1,  wlo + O1,  Ez, Mz, (size_t)Ez*Mz, 524288);
    split_w<<<dim3(Ez/256, Mz/16, Lz), 256>>>(w2, whi + O2,  wlo + O2,  Mz, Ez, (size_t)Mz*Ez, 524288);

    // 2. embedding + positional encoding
    embed_pe_kernel<<<(Nrows * Ez + 255) / 256, 256>>>(inputs, embed, px);

    dim3 gE(Ez / 128, Nrows / 128);
    dim3 gM(Mz / 128, Nrows / 128);
    dim3 gKV(Bz * Hz, KV_SPLITS);
    dim3 gND(Bz * Hz, Sz / 64);

    for (int l = 0; l < Lz; l++) {
        const uint32_t* wqh = whi + OQ  + (size_t)l * 131072;
        const uint32_t* wql = wlo + OQ  + (size_t)l * 131072;
        const uint32_t* wkh = whi + OK_ + (size_t)l * 131072;
        const uint32_t* wkl = wlo + OK_ + (size_t)l * 131072;
        const uint32_t* wvh = whi + OV  + (size_t)l * 131072;
        const uint32_t* wvl = wlo + OV  + (size_t)l * 131072;
        const uint32_t* woh = whi + OO  + (size_t)l * 131072;
        const uint32_t* wol = wlo + OO  + (size_t)l * 131072;
        const uint32_t* w1h = whi + O1  + (size_t)l * 524288;
        const uint32_t* w1l = wlo + O1  + (size_t)l * 524288;
        const uint32_t* w2h = whi + O2  + (size_t)l * 524288;
        const uint32_t* w2l = wlo + O2  + (size_t)l * 524288;

        layernorm_split<<<Nrows / 16, 256>>>(px, hAhi, hAlo,
                                             ln1_scale + l * Ez, ln1_bias + l * Ez);
        gemm_tc<1,0><<<gE, 256, SMEM_BYTES>>>(hAhi, hAlo, wqh, wql, pq, Ez, Ez,
                                              nullptr, nullptr, nullptr, nullptr, nullptr);
        gemm_tc<2,0><<<gE, 256, SMEM_BYTES>>>(hAhi, hAlo, wkh, wkl, pk, Ez, Ez,
                                              nullptr, nullptr, inputs, nullptr, nullptr);
        gemm_tc<0,0><<<gE, 256, SMEM_BYTES>>>(hAhi, hAlo, wvh, wvl, pv, Ez, Ez,
                                              nullptr, nullptr, nullptr, nullptr, nullptr);
        zero_kv_kernel<<<(Bz * Hz * Dz * Dz + 255) / 256, 256>>>(pkv, pz);
        kv_kernel<<<gKV, 256>>>(pk, pv, pkv, pz);
        numden_split<<<gND, 256>>>(pq, pkv, pz, ndhi, ndlo);
        gemm_tc<5,0><<<gE, 256, SMEM_BYTES>>>(ndhi, ndlo, woh, wol, px, Ez, Ez,
                                              nullptr, px, nullptr, nullptr, nullptr);
        layernorm_split<<<Nrows / 16, 256>>>(px, hAhi, hAlo,
                                             ln2_scale + l * Ez, ln2_bias + l * Ez);
        gemm_tc<3,1><<<gM, 256, SMEM_BYTES>>>(hAhi, hAlo, w1h, w1l, nullptr, Ez, Mz,
                                              b1 + (size_t)l * Mz, nullptr, nullptr, pthi, ptlo);
        gemm_tc<4,0><<<gE, 256, SMEM_BYTES>>>(pthi, ptlo, w2h, w2l, px, Mz, Ez,
                                              b2 + (size_t)l * Ez, px, nullptr, nullptr, nullptr);
    }

    layernorm_kernel<<<Nrows, 256>>>(px, out, lnf_scale, lnf_bias);
}

// round 7
// speedup vs baseline: 3.2258x; 1.0553x over previous
#include <cuda_runtime.h>
#include <cuda_bf16.h>
#include <math.h>
#include <stdint.h>

#define Bz 4
#define Sz 4096
#define Ez 512
#define Hz 8
#define Dz 64
#define Mz 2048
#define Lz 6
#define Nrows (Bz*Sz)
#define LN_EPS 1e-6f
#define KEPS 1e-3f

// ---------------- device scratch ----------------
__device__ float g_x[Nrows*Ez];
__device__ float g_phiq[Nrows*Ez];
__device__ float g_phik[Nrows*Ez];
__device__ float g_v[Nrows*Ez];
__device__ float g_kv[Bz*Hz*Dz*Dz];
__device__ float g_z[Bz*Hz*Dz];
// split-permuted activations (uint32 = packed bf16x2)
__device__ __align__(16) uint32_t g_hAhi[Nrows*256];
__device__ __align__(16) uint32_t g_hAlo[Nrows*256];
__device__ __align__(16) uint32_t g_ndhi[Nrows*256];
__device__ __align__(16) uint32_t g_ndlo[Nrows*256];
__device__ __align__(16) uint32_t g_pthi[Nrows*1024];
__device__ __align__(16) uint32_t g_ptlo[Nrows*1024];
// split-permuted weights:
//   fused qkv @0       (layer pitch 393216; q=colTiles0-3,k=4-7,v=8-11)
//   wo  @2359296       (layer pitch 131072)
//   w1  @3145728       (layer pitch 524288)
//   w2  @6291456       (layer pitch 524288)
#define OFQ 0
#define OO  2359296
#define O1  3145728
#define O2  6291456
#define WTOT 9437184
__device__ __align__(16) uint32_t g_whi[WTOT];
__device__ __align__(16) uint32_t g_wlo[WTOT];

// ---------------- helpers ----------------
__device__ __forceinline__ void split_pack(float x0, float x1,
                                           uint32_t& hi, uint32_t& lo) {
    __nv_bfloat162 h = __floats2bfloat162_rn(x0, x1);
    float r0 = x0 - __bfloat162float(h.x);
    float r1 = x1 - __bfloat162float(h.y);
    __nv_bfloat162 l = __floats2bfloat162_rn(r0, r1);
    hi = *reinterpret_cast<uint32_t*>(&h);
    lo = *reinterpret_cast<uint32_t*>(&l);
}
__device__ __forceinline__ void mma_bf16(float* c, uint4 a, uint2 b) {
    asm volatile(
        "mma.sync.aligned.m16n8k16.row.col.f32.bf16.bf16.f32 "
        "{%0,%1,%2,%3}, {%4,%5,%6,%7}, {%8,%9}, {%0,%1,%2,%3};"
        : "+f"(c[0]), "+f"(c[1]), "+f"(c[2]), "+f"(c[3])
        : "r"(a.x), "r"(a.y), "r"(a.z), "r"(a.w), "r"(b.x), "r"(b.y));
}
__device__ __forceinline__ float warp_sum(float v) {
    #pragma unroll
    for (int o = 16; o; o >>= 1) v += __shfl_xor_sync(0xffffffffu, v, o);
    return v;
}
__device__ __forceinline__ float gelu_tanh(float x) {
    float x3 = x * x * x;
    return 0.5f * x * (1.f + tanhf(0.7978845608028654f * (x + 0.044715f * x3)));
}
__device__ __forceinline__ void cp16(uint32_t dst, const void* src) {
    asm volatile("cp.async.cg.shared.global [%0], [%1], 16;\n" :: "r"(dst), "l"(src));
}
__device__ __forceinline__ void cp_commit() { asm volatile("cp.async.commit_group;\n"); }
template<int N>
__device__ __forceinline__ void cp_wait() {
    asm volatile("cp.async.wait_group %0;\n" :: "n"(N));
}

// ---------------- weight split pre-pass (permuted GEMM-B layout) -----------
__global__ void split_w(const float* __restrict__ W,
                        uint32_t* __restrict__ hi, uint32_t* __restrict__ lo,
                        int K, int NC, size_t wStrideL, size_t oStrideL) {
    int l = blockIdx.z;
    const float* Wl = W + (size_t)l * wStrideL;
    uint32_t* hiL = hi + (size_t)l * oStrideL;
    uint32_t* loL = lo + (size_t)l * oStrideL;
    int c = blockIdx.x * 256 + threadIdx.x;
    int kb = blockIdx.y;
    int cb = c >> 7, nb = (c >> 3) & 15, g = c & 7;
    int stage = kb >> 1, kbS = kb & 1;
    uint32_t h8[8], l8[8];
    #pragma unroll
    for (int o = 0; o < 8; o++) {
        int tq = o >> 1, hb = o & 1;
        int k = kb * 16 + 2 * tq + 8 * hb;
        split_pack(Wl[(size_t)k * NC + c], Wl[(size_t)(k + 1) * NC + c], h8[o], l8[o]);
    }
    size_t I = ((size_t)(cb * (K >> 5) + stage)) * 2048 + (kbS * 16 + nb) * 64 + g * 8;
    *(uint4*)&hiL[I]     = *(uint4*)&h8[0];
    *(uint4*)&hiL[I + 4] = *(uint4*)&h8[4];
    *(uint4*)&loL[I]     = *(uint4*)&l8[0];
    *(uint4*)&loL[I + 4] = *(uint4*)&l8[4];
}

// ---------------- embedding + PE ----------------
__global__ void embed_pe_kernel(const int* __restrict__ inp,
                                const float* __restrict__ emb,
                                float* __restrict__ x) {
    int idx = blockIdx.x * blockDim.x + threadIdx.x;
    if (idx >= Nrows * Ez) return;
    int e = idx & (Ez - 1);
    int n = idx >> 9;
    int s = n & (Sz - 1);
    int tok = inp[n];
    int j = (e >> 1) * 2;
    const float c = -9.210340371976184f / (float)Ez;
    float ang = (float)s * expf((float)j * c);
    float pe = (e & 1) ? cosf(ang) : sinf(ang);
    x[idx] = emb[(size_t)tok * Ez + e] + pe;
}

// ---------------- final plain layernorm ----------------
__device__ __forceinline__ float block_sum(float val, float* red) {
    __syncthreads();
    int t = threadIdx.x;
    #pragma unroll
    for (int o = 16; o; o >>= 1) val += __shfl_down_sync(0xffffffffu, val, o);
    if ((t & 31) == 0) red[t >> 5] = val;
    __syncthreads();
    if (t < 32) {
        float r = (t < 8) ? red[t] : 0.f;
        #pragma unroll
        for (int o = 4; o; o >>= 1) r += __shfl_down_sync(0xffffffffu, r, o);
        if (t == 0) red[0] = r;
    }
    __syncthreads();
    return red[0];
}
__global__ void layernorm_kernel(const float* __restrict__ in,
                                 float* __restrict__ out,
                                 const float* __restrict__ scale,
                                 const float* __restrict__ bias) {
    __shared__ float red[32];
    int n = blockIdx.x;
    int t = threadIdx.x;
    const float* row = in + (size_t)n * Ez;
    float2 v = *(const float2*)&row[t * 2];
    float mu = block_sum(v.x + v.y, red) * (1.f / Ez);
    float dx = v.x - mu, dy = v.y - mu;
    float var = block_sum(dx * dx + dy * dy, red) * (1.f / Ez);
    float rs = rsqrtf(var + LN_EPS);
    float2 o;
    o.x = dx * rs * scale[t * 2 + 0] + bias[t * 2 + 0];
    o.y = dy * rs * scale[t * 2 + 1] + bias[t * 2 + 1];
    *(float2*)&out[(size_t)n * Ez + t * 2] = o;
}

// ---------------- layernorm -> split-permuted output (16 rows/block) -------
__global__ void layernorm_split(const float* __restrict__ in,
                                uint32_t* __restrict__ outHi,
                                uint32_t* __restrict__ outLo,
                                const float* __restrict__ scale,
                                const float* __restrict__ bias) {
    __shared__ float nrm[16][516];
    int tid = threadIdx.x;
    int warp = tid >> 5, lane = tid & 31;
    long n0 = (long)blockIdx.x * 16;
    #pragma unroll
    for (int rr = 0; rr < 2; rr++) {
        int r = warp * 2 + rr;
        const float* row = in + (n0 + r) * Ez;
        float4 v[4];
        float s = 0.f;
        #pragma unroll
        for (int q = 0; q < 4; q++) {
            v[q] = *(const float4*)&row[lane * 4 + q * 128];
            s += v[q].x + v[q].y + v[q].z + v[q].w;
        }
        float mu = warp_sum(s) * (1.f / Ez);
        float vr = 0.f;
        #pragma unroll
        for (int q = 0; q < 4; q++) {
            float a = v[q].x - mu, b = v[q].y - mu, c = v[q].z - mu, d = v[q].w - mu;
            vr += a * a + b * b + c * c + d * d;
        }
        float rs = rsqrtf(warp_sum(vr) * (1.f / Ez) + LN_EPS);
        #pragma unroll
        for (int q = 0; q < 4; q++) {
            int c = lane * 4 + q * 128;
            float4 sc = *(const float4*)&scale[c];
            float4 bi = *(const float4*)&bias[c];
            float4 o;
            o.x = (v[q].x - mu) * rs * sc.x + bi.x;
            o.y = (v[q].y - mu) * rs * sc.y + bi.y;
            o.z = (v[q].z - mu) * rs * sc.z + bi.z;
            o.w = (v[q].w - mu) * rs * sc.w + bi.w;
            *(float4*)&nrm[r][c] = o;
        }
    }
    __syncthreads();
    int g = tid & 7, kb = (tid >> 3) & 1, stage = tid >> 4;
    uint32_t hi[16], lo[16];
    #pragma unroll
    for (int o = 0; o < 16; o++) {
        int tq = o >> 2, kbit = (o >> 1) & 1, rbit = o & 1;
        int c = stage * 32 + kb * 16 + 2 * tq + 8 * kbit;
        int rl = g + 8 * rbit;
        split_pack(nrm[rl][c], nrm[rl][c + 1], hi[o], lo[o]);
    }
    size_t I = ((size_t)((blockIdx.x >> 3) * 16 + stage)) * 2048
             + ((blockIdx.x & 7) * 2 + kb) * 128 + g * 16;
    *(uint4*)&outHi[I]      = *(uint4*)&hi[0];
    *(uint4*)&outHi[I + 4]  = *(uint4*)&hi[4];
    *(uint4*)&outHi[I + 8]  = *(uint4*)&hi[8];
    *(uint4*)&outHi[I + 12] = *(uint4*)&hi[12];
    *(uint4*)&outLo[I]      = *(uint4*)&lo[0];
    *(uint4*)&outLo[I + 4]  = *(uint4*)&lo[4];
    *(uint4*)&outLo[I + 8]  = *(uint4*)&lo[8];
    *(uint4*)&outLo[I + 12] = *(uint4*)&lo[12];
}

// ---------------- tensor-core GEMM: 3-stage cp.async, 1 sync/stage ---------
// EPI: 3 gelu(x+bias)->split OUT, 4 x+bias+resid, 5 x+resid, 6 fused qkv
// OUT: 0 fp32 C, 1 split-permuted outHi/outLo
#define SMEM_BYTES 98304
template<int EPI, int OUT>
__global__ void __launch_bounds__(256, 2)
gemm_tc(const uint32_t* __restrict__ Ahi, const uint32_t* __restrict__ Alo,
        const uint32_t* __restrict__ Bhi, const uint32_t* __restrict__ Blo,
        float* __restrict__ C, int K, int NC,
        const float* __restrict__ bias, const float* __restrict__ resid,
        const int* __restrict__ maskTok,
        uint32_t* __restrict__ outHi, uint32_t* __restrict__ outLo,
        float* __restrict__ oq, float* __restrict__ ok, float* __restrict__ ov) {
    extern __shared__ uint32_t sm[];
    const int tid = threadIdx.x;
    const int lane = tid & 31, warp = tid >> 5;
    const int wm = warp & 1, wn = warp >> 1;
    const int g = lane >> 2, tq = lane & 3;
    const int NS = K >> 5;
    const size_t aBase = (size_t)blockIdx.y * NS * 2048;
    const size_t bBase = (size_t)blockIdx.x * NS * 2048;
    const uint32_t smBase = (uint32_t)__cvta_generic_to_shared(sm);

    float acc[4][4][4];
    #pragma unroll
    for (int mt = 0; mt < 4; mt++)
        #pragma unroll
        for (int nt = 0; nt < 4; nt++)
            #pragma unroll
            for (int r = 0; r < 4; r++) acc[mt][nt][r] = 0.f;

    auto issue = [&](int s) {
        uint32_t d = smBase + (s % 3) * 32768 + tid * 16;
        const uint32_t* a1 = Ahi + aBase + (size_t)s * 2048 + tid * 4;
        const uint32_t* a2 = Alo + aBase + (size_t)s * 2048 + tid * 4;
        const uint32_t* b1 = Bhi + bBase + (size_t)s * 2048 + tid * 4;
        const uint32_t* b2 = Blo + bBase + (size_t)s * 2048 + tid * 4;
        cp16(d,          a1); cp16(d + 4096,  a1 + 1024);
        cp16(d + 8192,   a2); cp16(d + 12288, a2 + 1024);
        cp16(d + 16384,  b1); cp16(d + 20480, b1 + 1024);
        cp16(d + 24576,  b2); cp16(d + 28672, b2 + 1024);
    };

    issue(0); cp_commit();
    issue(1); cp_commit();

    for (int s = 0; s < NS; s++) {
        if (s + 1 < NS) cp_wait<1>(); else cp_wait<0>();
        __syncthreads();
        if (s + 2 < NS) { issue(s + 2); cp_commit(); }
        int base = (s % 3) * 8192;
        #pragma unroll
        for (int kb = 0; kb < 2; kb++) {
            uint4 Ah[4], Al[4]; uint2 Bh[4], Bl[4];
            #pragma unroll
            for (int mt = 0; mt < 4; mt++) {
                int blk = base + ((wm * 4 + mt) * 2 + kb) * 128 + lane * 4;
                Ah[mt] = *(uint4*)&sm[blk];
                Al[mt] = *(uint4*)&sm[blk + 2048];
            }
            #pragma unroll
            for (int nt = 0; nt < 4; nt++) {
                int bo = base + 4096 + (kb * 16 + wn * 4 + nt) * 64 + lane * 2;
                Bh[nt] = *(uint2*)&sm[bo];
                Bl[nt] = *(uint2*)&sm[bo + 2048];
            }
            #pragma unroll
            for (int mt = 0; mt < 4; mt++)
                #pragma unroll
                for (int nt = 0; nt < 4; nt++)
                    mma_bf16(acc[mt][nt], Ah[mt], Bh[nt]);
            #pragma unroll
            for (int mt = 0; mt < 4; mt++)
                #pragma unroll
                for (int nt = 0; nt < 4; nt++)
                    mma_bf16(acc[mt][nt], Ah[mt], Bl[nt]);
            #pragma unroll
            for (int mt = 0; mt < 4; mt++)
                #pragma unroll
                for (int nt = 0; nt < 4; nt++)
                    mma_bf16(acc[mt][nt], Al[mt], Bh[nt]);
        }
    }

    const long rowBase = (long)blockIdx.y * 128;
    const int colBase = blockIdx.x * 128;

    if (OUT == 1) {
        // w1: gelu(+bias) -> split-permuted
        #pragma unroll
        for (int mt = 0; mt < 4; mt++) {
            float tv[4][4];
            #pragma unroll
            for (int nt = 0; nt < 4; nt++) {
                int c = colBase + wn * 32 + nt * 8 + 2 * tq;
                float b0 = bias[c], b1 = bias[c + 1];
                tv[nt][0] = gelu_tanh(acc[mt][nt][0] + b0);
                tv[nt][1] = gelu_tanh(acc[mt][nt][1] + b1);
                tv[nt][2] = gelu_tanh(acc[mt][nt][2] + b0);
                tv[nt][3] = gelu_tanh(acc[mt][nt][3] + b1);
            }
            #pragma unroll
            for (int ntp = 0; ntp < 2; ntp++) {
                uint4 hv, lv;
                split_pack(tv[2*ntp][0],   tv[2*ntp][1],   hv.x, lv.x);
                split_pack(tv[2*ntp][2],   tv[2*ntp][3],   hv.y, lv.y);
                split_pack(tv[2*ntp+1][0], tv[2*ntp+1][1], hv.z, lv.z);
                split_pack(tv[2*ntp+1][2], tv[2*ntp+1][3], hv.w, lv.w);
                size_t I = ((size_t)blockIdx.y * (NC >> 5) + blockIdx.x * 4 + wn) * 2048
                         + ((wm * 4 + mt) * 2 + ntp) * 128 + g * 16 + tq * 4;
                *(uint4*)&outHi[I] = hv;
                *(uint4*)&outLo[I] = lv;
            }
        }
        return;
    }

    if (EPI == 6) {
        int mat = colBase >> 9;            // 0=q,1=k,2=v
        int cc0 = colBase & 511;
        float* dst = (mat == 0) ? oq : (mat == 1) ? ok : ov;
        #pragma unroll
        for (int mt = 0; mt < 4; mt++) {
            long r0 = rowBase + wm * 64 + mt * 16 + g;
            long r1 = r0 + 8;
            float m0 = 1.f, m1 = 1.f;
            if (mat == 1) {
                m0 = (maskTok[r0] > 0) ? 1.f : 0.f;
                m1 = (maskTok[r1] > 0) ? 1.f : 0.f;
            }
            #pragma unroll
            for (int nt = 0; nt < 4; nt++) {
                int c = cc0 + wn * 32 + nt * 8 + 2 * tq;
                float v0 = acc[mt][nt][0], v1 = acc[mt][nt][1];
                float v2 = acc[mt][nt][2], v3 = acc[mt][nt][3];
                if (mat == 0) {
                    v0 = fmaxf(v0, 0.f) + KEPS; v1 = fmaxf(v1, 0.f) + KEPS;
                    v2 = fmaxf(v2, 0.f) + KEPS; v3 = fmaxf(v3, 0.f) + KEPS;
                } else if (mat == 1) {
                    v0 = (fmaxf(v0, 0.f) + KEPS) * m0; v1 = (fmaxf(v1, 0.f) + KEPS) * m0;
                    v2 = (fmaxf(v2, 0.f) + KEPS) * m1; v3 = (fmaxf(v3, 0.f) + KEPS) * m1;
                }
                float2 o0 = {v0, v1}, o1 = {v2, v3};
                *(float2*)&dst[(size_t)r0 * 512 + c] = o0;
                *(float2*)&dst[(size_t)r1 * 512 + c] = o1;
            }
        }
        return;
    }

    #pragma unroll
    for (int mt = 0; mt < 4; mt++) {
        long r0 = rowBase + wm * 64 + mt * 16 + g;
        long r1 = r0 + 8;
        #pragma unroll
        for (int nt = 0; nt < 4; nt++) {
            int c = colBase + wn * 32 + nt * 8 + 2 * tq;
            float v0 = acc[mt][nt][0], v1 = acc[mt][nt][1];
            float v2 = acc[mt][nt][2], v3 = acc[mt][nt][3];
            if (EPI == 4) {
                float b0 = bias[c], b1 = bias[c + 1];
                v0 += b0; v1 += b1; v2 += b0; v3 += b1;
            }
            v0 += resid[(size_t)r0 * NC + c];
            v1 += resid[(size_t)r0 * NC + c + 1];
            v2 += resid[(size_t)r1 * NC + c];
            v3 += resid[(size_t)r1 * NC + c + 1];
            float2 o0 = {v0, v1}, o1 = {v2, v3};
            *(float2*)&C[(size_t)r0 * NC + c] = o0;
            *(float2*)&C[(size_t)r1 * NC + c] = o1;
        }
    }
}

// ---------------- zero kv/z ----------------
__global__ void zero_kv_kernel(float* kv, float* z) {
    int i = blockIdx.x * blockDim.x + threadIdx.x;
    if (i < Bz * Hz * Dz * Dz) kv[i] = 0.f;
    if (i < Bz * Hz * Dz) z[i] = 0.f;
}

// ---------------- kv = phik^T @ v, z = sum phik ----------------
#define KV_SPLITS 8
__global__ void kv_kernel(const float* __restrict__ phik,
                          const float* __restrict__ v,
                          float* __restrict__ kv, float* __restrict__ z) {
    int bh = blockIdx.x, split = blockIdx.y;
    int b = bh >> 3, h = bh & 7;
    const int CH = Sz / KV_SPLITS;
    int s0 = split * CH;
    __shared__ float ks[32][64];
    __shared__ float vs[32][64];
    int tid = threadIdx.x;
    int tx = tid & 15, ty = tid >> 4;
    float acc[4][4];
    #pragma unroll
    for (int i = 0; i < 4; i++)
        #pragma unroll
        for (int j = 0; j < 4; j++) acc[i][j] = 0.f;
    float zacc[4] = {0.f, 0.f, 0.f, 0.f};
    for (int c = 0; c < CH; c += 32) {
        #pragma unroll
        for (int r = 0; r < 2; r++) {
            int f4 = tid + r * 256;
            int row = f4 >> 4, col = (f4 & 15) * 4;
            size_t base = ((size_t)(b * Sz + s0 + c + row)) * Ez + h * 64 + col;
            *(float4*)&ks[row][col] = *(const float4*)&phik[base];
            *(float4*)&vs[row][col] = *(const float4*)&v[base];
        }
        __syncthreads();
        #pragma unroll
        for (int s = 0; s < 32; s++) {
            float a[4], bb[4];
            #pragma unroll
            for (int i = 0; i < 4; i++) { a[i] = ks[s][ty * 4 + i]; bb[i] = vs[s][tx * 4 + i]; }
            #pragma unroll
            for (int i = 0; i < 4; i++)
                #pragma unroll
                for (int j = 0; j < 4; j++) acc[i][j] = fmaf(a[i], bb[j], acc[i][j]);
            if (tx == 0)
                #pragma unroll
                for (int i = 0; i < 4; i++) zacc[i] += a[i];
        }
        __syncthreads();
    }
    float* kvp = kv + bh * Dz * Dz;
    #pragma unroll
    for (int i = 0; i < 4; i++)
        #pragma unroll
        for (int j = 0; j < 4; j++)
            atomicAdd(&kvp[(ty * 4 + i) * 64 + tx * 4 + j], acc[i][j]);
    if (tx == 0)
        #pragma unroll
        for (int i = 0; i < 4; i++)
            atomicAdd(&z[bh * 64 + ty * 4 + i], zacc[i]);
}

// ---------------- numden -> split-permuted ----------------
__global__ void numden_split(const float* __restrict__ phiq,
                             const float* __restrict__ kv,
                             const float* __restrict__ z,
                             uint32_t* __restrict__ outHi,
                             uint32_t* __restrict__ outLo) {
    int bh = blockIdx.x, chunk = blockIdx.y;
    int b = bh >> 3, h = bh & 7;
    __shared__ float kvs[64][65];
    __shared__ float zs[64];
    __shared__ float pqs[4][64];
    __shared__ float nd[64][65];
    int tid = threadIdx.x;
    int tx = tid & 63, ty = tid >> 6;
    for (int idx = tid; idx < 4096; idx += 256)
        kvs[idx >> 6][idx & 63] = kv[bh * Dz * Dz + idx];
    if (tid < 64) zs[tid] = z[bh * 64 + tid];
    __syncthreads();
    int s0 = chunk * 64;
    for (int it = 0; it < 16; it++) {
        int sl = it * 4 + ty;
        size_t base = ((size_t)(b * Sz + s0 + sl)) * Ez + h * 64;
        pqs[ty][tx] = phiq[base + tx];
        __syncthreads();
        float num = 0.f, den = 0.f;
        #pragma unroll
        for (int m = 0; m < 64; m++) {
            float p = pqs[ty][m];
            num = fmaf(p, kvs[m][tx], num);
            den = fmaf(p, zs[m], den);
        }
        nd[sl][tx] = num / den;
        __syncthreads();
    }
    int g = tid & 7, halfRun = (tid >> 3) & 1, kb = (tid >> 4) & 1;
    int s2 = (tid >> 5) & 1, mtl = tid >> 6;
    long rowTile = ((long)b * Sz + chunk * 64) >> 7;
    int mtG = (chunk & 1) * 4 + mtl;
    int stage = h * 2 + s2;
    uint32_t hi[8], lo[8];
    #pragma unroll
    for (int o = 0; o < 8; o++) {
        int tqv = halfRun * 2 + (o >> 2);
        int kbit = (o >> 1) & 1, rbit = o & 1;
        int rl = mtl * 16 + g + 8 * rbit;
        int cl = s2 * 32 + kb * 16 + 2 * tqv + 8 * kbit;
        split_pack(nd[rl][cl], nd[rl][cl + 1], hi[o], lo[o]);
    }
    size_t I = ((size_t)(rowTile * 16 + stage)) * 2048
             + (mtG * 2 + kb) * 128 + g * 16 + halfRun * 8;
    *(uint4*)&outHi[I]     = *(uint4*)&hi[0];
    *(uint4*)&outHi[I + 4] = *(uint4*)&hi[4];
    *(uint4*)&outLo[I]     = *(uint4*)&lo[0];
    *(uint4*)&outLo[I + 4] = *(uint4*)&lo[4];
}

// ---------------- host ----------------
extern "C" void kernel_launch(void* const* d_in, const int* in_sizes, int n_in,
                              void* d_out, int out_size) {
    const int*   inputs    = (const int*)  d_in[0];
    const float* embed     = (const float*)d_in[1];
    const float* ln1_scale = (const float*)d_in[2];
    const float* ln1_bias  = (const float*)d_in[3];
    const float* wq        = (const float*)d_in[4];
    const float* wk        = (const float*)d_in[5];
    const float* wv        = (const float*)d_in[6];
    const float* wo        = (const float*)d_in[7];
    const float* ln2_scale = (const float*)d_in[8];
    const float* ln2_bias  = (const float*)d_in[9];
    const float* w1        = (const float*)d_in[10];
    const float* b1        = (const float*)d_in[11];
    const float* w2        = (const float*)d_in[12];
    const float* b2        = (const float*)d_in[13];
    const float* lnf_scale = (const float*)d_in[14];
    const float* lnf_bias  = (const float*)d_in[15];
    float* out = (float*)d_out;

    static float *px = nullptr, *pq, *pk, *pv, *pkv, *pz;
    static uint32_t *hAhi, *hAlo, *ndhi, *ndlo, *pthi, *ptlo, *whi, *wlo;
    if (!px) {
        cudaGetSymbolAddress((void**)&px,   g_x);
        cudaGetSymbolAddress((void**)&pq,   g_phiq);
        cudaGetSymbolAddress((void**)&pk,   g_phik);
        cudaGetSymbolAddress((void**)&pv,   g_v);
        cudaGetSymbolAddress((void**)&pkv,  g_kv);
        cudaGetSymbolAddress((void**)&pz,   g_z);
        cudaGetSymbolAddress((void**)&hAhi, g_hAhi);
        cudaGetSymbolAddress((void**)&hAlo, g_hAlo);
        cudaGetSymbolAddress((void**)&ndhi, g_ndhi);
        cudaGetSymbolAddress((void**)&ndlo, g_ndlo);
        cudaGetSymbolAddress((void**)&pthi, g_pthi);
        cudaGetSymbolAddress((void**)&ptlo, g_ptlo);
        cudaGetSymbolAddress((void**)&whi,  g_whi);
        cudaGetSymbolAddress((void**)&wlo,  g_wlo);
        cudaFuncSetAttribute(gemm_tc<6,0>, cudaFuncAttributeMaxDynamicSharedMemorySize, SMEM_BYTES);
        cudaFuncSetAttribute(gemm_tc<5,0>, cudaFuncAttributeMaxDynamicSharedMemorySize, SMEM_BYTES);
        cudaFuncSetAttribute(gemm_tc<3,1>, cudaFuncAttributeMaxDynamicSharedMemorySize, SMEM_BYTES);
        cudaFuncSetAttribute(gemm_tc<4,0>, cudaFuncAttributeMaxDynamicSharedMemorySize, SMEM_BYTES);
    }

    dim3 gQKV(12, Nrows / 128);
    dim3 gE(4, Nrows / 128);
    dim3 gM(16, Nrows / 128);
    dim3 gKV(Bz * Hz, KV_SPLITS);
    dim3 gND(Bz * Hz, Sz / 64);

    // launches 0-2: qkv splits; 3: embed; 4: ln1(l0); 5: fused qkv gemm (ncu -s 5)
    split_w<<<dim3(2, 32, Lz), 256>>>(wq, whi + OFQ,          wlo + OFQ,          Ez, Ez, (size_t)Ez*Ez, 393216);
    split_w<<<dim3(2, 32, Lz), 256>>>(wk, whi + OFQ + 131072, wlo + OFQ + 131072, Ez, Ez, (size_t)Ez*Ez, 393216);
    split_w<<<dim3(2, 32, Lz), 256>>>(wv, whi + OFQ + 262144, wlo + OFQ + 262144, Ez, Ez, (size_t)Ez*Ez, 393216);
    embed_pe_kernel<<<(Nrows * Ez + 255) / 256, 256>>>(inputs, embed, px);
    layernorm_split<<<Nrows / 16, 256>>>(px, hAhi, hAlo, ln1_scale, ln1_bias);
    gemm_tc<6,0><<<gQKV, 256, SMEM_BYTES>>>(hAhi, hAlo, whi + OFQ, wlo + OFQ,
                                            nullptr, Ez, 512, nullptr, nullptr, inputs,
                                            nullptr, nullptr, pq, pk, pv);
    split_w<<<dim3(2, 32, Lz), 256>>>(wo, whi + OO, wlo + OO, Ez, Ez, (size_t)Ez*Ez, 131072);
    split_w<<<dim3(8, 32, Lz), 256>>>(w1, whi + O1, wlo + O1, Ez, Mz, (size_t)Ez*Mz, 524288);
    split_w<<<dim3(2, 128, Lz), 256>>>(w2, whi + O2, wlo + O2, Mz, Ez, (size_t)Mz*Ez, 524288);

    for (int l = 0; l < Lz; l++) {
        const uint32_t* fqh = whi + OFQ + (size_t)l * 393216;
        const uint32_t* fql = wlo + OFQ + (size_t)l * 393216;
        const uint32_t* woh = whi + OO + (size_t)l * 131072;
        const uint32_t* wol = wlo + OO + (size_t)l * 131072;
        const uint32_t* w1h = whi + O1 + (size_t)l * 524288;
        const uint32_t* w1l = wlo + O1 + (size_t)l * 524288;
        const uint32_t* w2h = whi + O2 + (size_t)l * 524288;
        const uint32_t* w2l = wlo + O2 + (size_t)l * 524288;

        if (l > 0) {
            layernorm_split<<<Nrows / 16, 256>>>(px, hAhi, hAlo,
                                                 ln1_scale + l * Ez, ln1_bias + l * Ez);
            gemm_tc<6,0><<<gQKV, 256, SMEM_BYTES>>>(hAhi, hAlo, fqh, fql,
                                                    nullptr, Ez, 512, nullptr, nullptr, inputs,
                                                    nullptr, nullptr, pq, pk, pv);
        }
        zero_kv_kernel<<<(Bz * Hz * Dz * Dz + 255) / 256, 256>>>(pkv, pz);
        kv_kernel<<<gKV, 256>>>(pk, pv, pkv, pz);
        numden_split<<<gND, 256>>>(pq, pkv, pz, ndhi, ndlo);
        gemm_tc<5,0><<<gE, 256, SMEM_BYTES>>>(ndhi, ndlo, woh, wol, px, Ez, Ez,
                                              nullptr, px, nullptr, nullptr, nullptr,
                                              nullptr, nullptr, nullptr);
        layernorm_split<<<Nrows / 16, 256>>>(px, hAhi, hAlo,
                                             ln2_scale + l * Ez, ln2_bias + l * Ez);
        gemm_tc<3,1><<<gM, 256, SMEM_BYTES>>>(hAhi, hAlo, w1h, w1l, nullptr, Ez, Mz,
                                              b1 + (size_t)l * Mz, nullptr, nullptr,
                                              pthi, ptlo, nullptr, nullptr, nullptr);
        gemm_tc<4,0><<<gE, 256, SMEM_BYTES>>>(pthi, ptlo, w2h, w2l, px, Mz, Ez,
                                              b2 + (size_t)l * Ez, px, nullptr,
                                              nullptr, nullptr, nullptr, nullptr, nullptr);
    }

    layernorm_kernel<<<Nrows, 256>>>(px, out, lnf_scale, lnf_bias);
}